// round 1
// baseline (speedup 1.0000x reference)
#include <cuda_runtime.h>
#include <math.h>

#define D_MODEL 1024
#define NHEADS  16
#define HDIM    64
#define BATCH   2
#define SEQ     2048
#define MTOT    (BATCH*SEQ)
#define SCALE   8.0f      // reference divides by head_dim**-0.5 => multiply by sqrt(64)

// ---------------- scratch (device globals: no allocation allowed) ----------------
__device__ float g_q[(size_t)MTOT * D_MODEL];     // [B,H,S,Hd]
__device__ float g_k[(size_t)MTOT * D_MODEL];     // [B,H,S,Hd]
__device__ float g_v[(size_t)MTOT * D_MODEL];     // [B,H,S,Hd]
__device__ float g_attn[(size_t)MTOT * D_MODEL];  // [B,S,D] (heads re-merged)

// =====================================================================
// GEMM body: C[M,N] = X[M,K] @ W[N,K]^T + bias,  M=4096, N=K=1024
// BM=BN=128, BK=16, 256 threads, 8x8 micro-tile per thread.
// SPLIT_HEADS: scatter columns into [B,H,S,Hd] layout.
// =====================================================================
template<bool SPLIT_HEADS>
__device__ __forceinline__ void gemm_body(
    const float* __restrict__ X, const float* __restrict__ W,
    const float* __restrict__ bias, float* __restrict__ out)
{
    const int K = D_MODEL;
    __shared__ float Xs[16][132];   // [k][m], pitch 132 (16B-aligned rows)
    __shared__ float Ws[16][132];   // [k][n]

    const int tid = threadIdx.x;
    const int tx  = tid & 15;       // n micro-tile
    const int ty  = tid >> 4;       // m micro-tile
    const int m0  = blockIdx.y * 128;
    const int n0  = blockIdx.x * 128;
    const int lr  = tid >> 1;       // 0..127 load row
    const int lc  = (tid & 1) * 8;  // 0 or 8 load col group

    float acc[8][8];
    #pragma unroll
    for (int i = 0; i < 8; i++)
        #pragma unroll
        for (int j = 0; j < 8; j++) acc[i][j] = 0.f;

    for (int k0 = 0; k0 < K; k0 += 16) {
        float4 x0 = *reinterpret_cast<const float4*>(X + (size_t)(m0+lr)*K + k0 + lc);
        float4 x1 = *reinterpret_cast<const float4*>(X + (size_t)(m0+lr)*K + k0 + lc + 4);
        float4 w0 = *reinterpret_cast<const float4*>(W + (size_t)(n0+lr)*K + k0 + lc);
        float4 w1 = *reinterpret_cast<const float4*>(W + (size_t)(n0+lr)*K + k0 + lc + 4);
        Xs[lc+0][lr]=x0.x; Xs[lc+1][lr]=x0.y; Xs[lc+2][lr]=x0.z; Xs[lc+3][lr]=x0.w;
        Xs[lc+4][lr]=x1.x; Xs[lc+5][lr]=x1.y; Xs[lc+6][lr]=x1.z; Xs[lc+7][lr]=x1.w;
        Ws[lc+0][lr]=w0.x; Ws[lc+1][lr]=w0.y; Ws[lc+2][lr]=w0.z; Ws[lc+3][lr]=w0.w;
        Ws[lc+4][lr]=w1.x; Ws[lc+5][lr]=w1.y; Ws[lc+6][lr]=w1.z; Ws[lc+7][lr]=w1.w;
        __syncthreads();

        #pragma unroll
        for (int kk = 0; kk < 16; kk++) {
            float a[8], b[8];
            *reinterpret_cast<float4*>(&a[0]) = *reinterpret_cast<const float4*>(&Xs[kk][ty*8]);
            *reinterpret_cast<float4*>(&a[4]) = *reinterpret_cast<const float4*>(&Xs[kk][ty*8+4]);
            *reinterpret_cast<float4*>(&b[0]) = *reinterpret_cast<const float4*>(&Ws[kk][tx*8]);
            *reinterpret_cast<float4*>(&b[4]) = *reinterpret_cast<const float4*>(&Ws[kk][tx*8+4]);
            #pragma unroll
            for (int i = 0; i < 8; i++)
                #pragma unroll
                for (int j = 0; j < 8; j++)
                    acc[i][j] += a[i] * b[j];
        }
        __syncthreads();
    }

    float bv[8];
    #pragma unroll
    for (int j = 0; j < 8; j++) bv[j] = bias[n0 + tx*8 + j];

    if (SPLIT_HEADS) {
        // columns tx*8..tx*8+7 never straddle a 64-wide head boundary
        const int ncol0 = n0 + tx*8;
        const int h_ = ncol0 / HDIM;
        const int d0 = ncol0 % HDIM;
        #pragma unroll
        for (int i = 0; i < 8; i++) {
            const int m  = m0 + ty*8 + i;
            const int b_ = m >> 11;        // / SEQ
            const int s_ = m & (SEQ - 1);
            float* dst = out + (((size_t)(b_*NHEADS + h_) * SEQ + s_) * HDIM) + d0;
            float4 o0 = make_float4(acc[i][0]+bv[0], acc[i][1]+bv[1], acc[i][2]+bv[2], acc[i][3]+bv[3]);
            float4 o1 = make_float4(acc[i][4]+bv[4], acc[i][5]+bv[5], acc[i][6]+bv[6], acc[i][7]+bv[7]);
            *reinterpret_cast<float4*>(dst)     = o0;
            *reinterpret_cast<float4*>(dst + 4) = o1;
        }
    } else {
        #pragma unroll
        for (int i = 0; i < 8; i++) {
            float* dst = out + (size_t)(m0 + ty*8 + i) * D_MODEL + n0 + tx*8;
            float4 o0 = make_float4(acc[i][0]+bv[0], acc[i][1]+bv[1], acc[i][2]+bv[2], acc[i][3]+bv[3]);
            float4 o1 = make_float4(acc[i][4]+bv[4], acc[i][5]+bv[5], acc[i][6]+bv[6], acc[i][7]+bv[7]);
            *reinterpret_cast<float4*>(dst)     = o0;
            *reinterpret_cast<float4*>(dst + 4) = o1;
        }
    }
}

// Fused Q/K/V projection: grid.z selects which projection
__global__ __launch_bounds__(256) void qkv_proj_kernel(
    const float* __restrict__ q, const float* __restrict__ k, const float* __restrict__ v,
    const float* __restrict__ Wq, const float* __restrict__ bq,
    const float* __restrict__ Wk, const float* __restrict__ bk,
    const float* __restrict__ Wv, const float* __restrict__ bv)
{
    if (blockIdx.z == 0)      gemm_body<true>(q, Wq, bq, g_q);
    else if (blockIdx.z == 1) gemm_body<true>(k, Wk, bk, g_k);
    else                      gemm_body<true>(v, Wv, bv, g_v);
}

__global__ __launch_bounds__(256) void out_proj_kernel(
    const float* __restrict__ Wo, const float* __restrict__ bo, float* __restrict__ out)
{
    gemm_body<false>(g_attn, Wo, bo, out);
}

// =====================================================================
// Flash attention: one block per (bh, q-tile of 64). 64x64 k-tiles.
// 256 threads (16x16), 4x4 micro-tiles. Online softmax, fp32.
// Smem: Qs(64xFP), KP(64xFP: K tile, reused for P tile), Vs(64xFP), red(64x16)
// =====================================================================
#define FP 68   // row pitch (floats): 272B rows -> 16B-aligned float4 fragments
#define FLASH_SMEM_BYTES ((3*64*FP + 64*16) * (int)sizeof(float))

__global__ __launch_bounds__(256) void flash_attn_kernel()
{
    extern __shared__ float sm[];
    float* Qs  = sm;                 // 64*FP
    float* KP  = Qs + 64*FP;         // 64*FP  (K tile, then P tile)
    float* Vs  = KP + 64*FP;         // 64*FP
    float* red = Vs + 64*FP;         // 64*16

    const int tid = threadIdx.x;
    const int tx  = tid & 15;
    const int ty  = tid >> 4;
    const int q0  = blockIdx.x * 64;
    const int bh  = blockIdx.y;      // b*NHEADS + h

    const float* qb  = g_q + ((size_t)bh * SEQ + q0) * HDIM;
    const float* kb0 = g_k + (size_t)bh * SEQ * HDIM;
    const float* vb0 = g_v + (size_t)bh * SEQ * HDIM;

    // load Q tile (64 x 64)
    {
        const int r = tid >> 4;        // 0..15
        const int c = (tid & 15) * 4;  // 0..60
        #pragma unroll
        for (int rr = 0; rr < 4; rr++) {
            float4 qv = *reinterpret_cast<const float4*>(qb + (size_t)(r + rr*16) * HDIM + c);
            float* p = Qs + (r + rr*16) * FP + c;
            p[0]=qv.x; p[1]=qv.y; p[2]=qv.z; p[3]=qv.w;
        }
    }

    float acc[4][4];
    #pragma unroll
    for (int i = 0; i < 4; i++)
        #pragma unroll
        for (int j = 0; j < 4; j++) acc[i][j] = 0.f;
    float mrow[4], lrow[4];
    #pragma unroll
    for (int i = 0; i < 4; i++) { mrow[i] = -1e30f; lrow[i] = 0.f; }

    __syncthreads();

    for (int kt = 0; kt < SEQ/64; kt++) {
        const float* kb = kb0 + (size_t)kt * 64 * HDIM;
        const float* vb = vb0 + (size_t)kt * 64 * HDIM;
        {
            const int r = tid >> 4;
            const int c = (tid & 15) * 4;
            #pragma unroll
            for (int rr = 0; rr < 4; rr++) {
                float4 kv = *reinterpret_cast<const float4*>(kb + (size_t)(r + rr*16) * HDIM + c);
                float4 vv = *reinterpret_cast<const float4*>(vb + (size_t)(r + rr*16) * HDIM + c);
                float* kp = KP + (r + rr*16) * FP + c;
                kp[0]=kv.x; kp[1]=kv.y; kp[2]=kv.z; kp[3]=kv.w;
                float* vp = Vs + (r + rr*16) * FP + c;
                vp[0]=vv.x; vp[1]=vv.y; vp[2]=vv.z; vp[3]=vv.w;
            }
        }
        __syncthreads();

        // S = (Q K^T) * SCALE
        float s[4][4];
        #pragma unroll
        for (int i = 0; i < 4; i++)
            #pragma unroll
            for (int j = 0; j < 4; j++) s[i][j] = 0.f;

        #pragma unroll
        for (int d = 0; d < HDIM; d += 4) {
            float4 a4[4], b4[4];
            #pragma unroll
            for (int i = 0; i < 4; i++)
                a4[i] = *reinterpret_cast<const float4*>(Qs + (ty*4+i)*FP + d);
            #pragma unroll
            for (int j = 0; j < 4; j++)
                b4[j] = *reinterpret_cast<const float4*>(KP + (tx*4+j)*FP + d);
            #pragma unroll
            for (int i = 0; i < 4; i++)
                #pragma unroll
                for (int j = 0; j < 4; j++) {
                    s[i][j] += a4[i].x*b4[j].x;
                    s[i][j] += a4[i].y*b4[j].y;
                    s[i][j] += a4[i].z*b4[j].z;
                    s[i][j] += a4[i].w*b4[j].w;
                }
        }

        // tile row-max (scaled)
        float tmax[4];
        #pragma unroll
        for (int i = 0; i < 4; i++) {
            tmax[i] = -1e30f;
            #pragma unroll
            for (int j = 0; j < 4; j++) {
                s[i][j] *= SCALE;
                tmax[i] = fmaxf(tmax[i], s[i][j]);
            }
            red[(ty*4+i)*16 + tx] = tmax[i];
        }
        __syncthreads();   // (A) all K reads done; red(max) ready

        float alpha[4], psum[4];
        #pragma unroll
        for (int i = 0; i < 4; i++) {
            const int row = ty*4 + i;
            float mt = red[row*16 + 0];
            #pragma unroll
            for (int t = 1; t < 16; t++) mt = fmaxf(mt, red[row*16 + t]);
            const float mnew = fmaxf(mrow[i], mt);
            alpha[i] = __expf(mrow[i] - mnew);
            mrow[i] = mnew;
            float p0 = __expf(s[i][0] - mnew);
            float p1 = __expf(s[i][1] - mnew);
            float p2 = __expf(s[i][2] - mnew);
            float p3 = __expf(s[i][3] - mnew);
            psum[i] = (p0 + p1) + (p2 + p3);
            // P tile overwrites K tile (safe: K reads finished before sync A)
            *reinterpret_cast<float4*>(KP + row*FP + tx*4) = make_float4(p0, p1, p2, p3);
        }
        __syncthreads();   // (B) red(max) reads done; P tile fully written

        #pragma unroll
        for (int i = 0; i < 4; i++) red[(ty*4+i)*16 + tx] = psum[i];
        __syncthreads();   // (C) red(sum) ready

        #pragma unroll
        for (int i = 0; i < 4; i++) {
            const int row = ty*4 + i;
            float ts = 0.f;
            #pragma unroll
            for (int t = 0; t < 16; t++) ts += red[row*16 + t];
            lrow[i] = lrow[i]*alpha[i] + ts;
            #pragma unroll
            for (int j = 0; j < 4; j++) acc[i][j] *= alpha[i];
        }

        // O += P * V
        #pragma unroll
        for (int k = 0; k < 64; k += 4) {
            float4 p4[4];
            #pragma unroll
            for (int i = 0; i < 4; i++)
                p4[i] = *reinterpret_cast<const float4*>(KP + (ty*4+i)*FP + k);
            #pragma unroll
            for (int kk = 0; kk < 4; kk++) {
                float4 v4 = *reinterpret_cast<const float4*>(Vs + (k+kk)*FP + tx*4);
                #pragma unroll
                for (int i = 0; i < 4; i++) {
                    const float p = reinterpret_cast<const float*>(&p4[i])[kk];
                    acc[i][0] += p * v4.x;
                    acc[i][1] += p * v4.y;
                    acc[i][2] += p * v4.z;
                    acc[i][3] += p * v4.w;
                }
            }
        }
        __syncthreads();   // (D) protect KP/Vs/red for next iteration
    }

    const int b_ = bh / NHEADS;
    const int h_ = bh % NHEADS;
    #pragma unroll
    for (int i = 0; i < 4; i++) {
        const int q = q0 + ty*4 + i;
        const float inv = 1.0f / lrow[i];
        float* dst = g_attn + ((size_t)(b_*SEQ + q)) * D_MODEL + h_*HDIM + tx*4;
        *reinterpret_cast<float4*>(dst) =
            make_float4(acc[i][0]*inv, acc[i][1]*inv, acc[i][2]*inv, acc[i][3]*inv);
    }
}

// =====================================================================
extern "C" void kernel_launch(void* const* d_in, const int* in_sizes, int n_in,
                              void* d_out, int out_size)
{
    const float* query = (const float*)d_in[0];
    const float* key   = (const float*)d_in[1];
    const float* value = (const float*)d_in[2];
    const float* Wq    = (const float*)d_in[3];
    const float* bq    = (const float*)d_in[4];
    const float* Wk    = (const float*)d_in[5];
    const float* bk    = (const float*)d_in[6];
    const float* Wv    = (const float*)d_in[7];
    const float* bv    = (const float*)d_in[8];
    const float* Wo    = (const float*)d_in[9];
    const float* bo    = (const float*)d_in[10];
    float* out = (float*)d_out;

    cudaFuncSetAttribute(flash_attn_kernel,
                         cudaFuncAttributeMaxDynamicSharedMemorySize, FLASH_SMEM_BYTES);

    dim3 qkv_grid(D_MODEL/128, MTOT/128, 3);   // (8, 32, 3)
    qkv_proj_kernel<<<qkv_grid, 256>>>(query, key, value, Wq, bq, Wk, bk, Wv, bv);

    dim3 attn_grid(SEQ/64, BATCH*NHEADS);      // (32, 32)
    flash_attn_kernel<<<attn_grid, 256, FLASH_SMEM_BYTES>>>();

    dim3 oproj_grid(D_MODEL/128, MTOT/128);    // (8, 32)
    out_proj_kernel<<<oproj_grid, 256>>>(Wo, bo, out);
}

// round 5
// speedup vs baseline: 1.2629x; 1.2629x over previous
#include <cuda_runtime.h>
#include <cuda_bf16.h>
#include <mma.h>
#include <math.h>
#include <stdint.h>

using namespace nvcuda;

#define D_MODEL 1024
#define NHEADS  16
#define HDIM    64
#define BATCH   2
#define SEQ     2048
#define MTOT    (BATCH*SEQ)
#define SCALE   8.0f      // reference divides by head_dim**-0.5 => multiply by sqrt(64)

// ---------------- scratch (device globals: no allocation allowed) ----------------
__device__ float g_q[(size_t)MTOT * D_MODEL];     // [B,H,S,Hd]
__device__ float g_k[(size_t)MTOT * D_MODEL];     // [B,H,S,Hd]
__device__ float g_v[(size_t)MTOT * D_MODEL];     // [B,H,S,Hd]
__device__ float g_attn[(size_t)MTOT * D_MODEL];  // [B,S,D] (heads re-merged)

// 2-term bf16 split: x ~= hi + lo, |err| ~ 2^-17 |x|
__device__ __forceinline__ void split2(float x, __nv_bfloat16& h, __nv_bfloat16& l) {
    h = __float2bfloat16(x);
    l = __float2bfloat16(x - __bfloat162float(h));
}

// =====================================================================
// wmma bf16-split GEMM: C[M,N] = X[M,K] @ W[N,K]^T + bias
// BM=BN=128, BK=32, 256 threads, 8 warps (4m x 2n), warp tile 32x64.
// =====================================================================
#define GP 48    // bf16 stage pitch (96B rows, 32B-aligned, mult of 16)
#define CP 136   // f32 epilogue pitch (544B rows, mult of 4)
#define GEMM_SMEM (128*CP*4 + 512)   // Csm (69632) + bias (512); stages (49152) alias Csm

template<bool SPLIT_HEADS>
__device__ __forceinline__ void gemm_wmma_body(
    const float* __restrict__ X, const float* __restrict__ W,
    const float* __restrict__ bias, float* __restrict__ out)
{
    extern __shared__ __align__(128) char smem[];
    __nv_bfloat16* Ah = reinterpret_cast<__nv_bfloat16*>(smem);
    __nv_bfloat16* Al = Ah + 128*GP;
    __nv_bfloat16* Bh = Al + 128*GP;
    __nv_bfloat16* Bl = Bh + 128*GP;
    float* Csm    = reinterpret_cast<float*>(smem);            // alias (used after mainloop)
    float* bias_s = reinterpret_cast<float*>(smem + 128*CP*4); // separate tail

    const int tid = threadIdx.x;
    const int wid = tid >> 5;
    const int m0  = blockIdx.y * 128;
    const int n0  = blockIdx.x * 128;
    const int row = tid >> 1;            // 0..127
    const int c0  = (tid & 1) * 16;      // float offset within 32-wide k-slab
    const int mw  = wid >> 1;            // 0..3
    const int nw  = wid & 1;             // 0..1

    if (tid < 128) bias_s[tid] = bias[n0 + tid];

    wmma::fragment<wmma::accumulator,16,16,16,float> acc[2][4];
    #pragma unroll
    for (int mi = 0; mi < 2; mi++)
        #pragma unroll
        for (int ni = 0; ni < 4; ni++) wmma::fill_fragment(acc[mi][ni], 0.f);

    const float* Ar = X + (size_t)(m0 + row) * D_MODEL + c0;
    const float* Br = W + (size_t)(n0 + row) * D_MODEL + c0;

    float4 ra[4], rb[4];
    #pragma unroll
    for (int j = 0; j < 4; j++) {
        ra[j] = *reinterpret_cast<const float4*>(Ar + j*4);
        rb[j] = *reinterpret_cast<const float4*>(Br + j*4);
    }

    for (int s = 0; s < D_MODEL/32; s++) {
        __syncthreads();   // previous iteration's MMA reads complete
        #pragma unroll
        for (int j = 0; j < 4; j++) {
            __nv_bfloat16 h0,h1,h2,h3,l0,l1,l2,l3;
            split2(ra[j].x,h0,l0); split2(ra[j].y,h1,l1);
            split2(ra[j].z,h2,l2); split2(ra[j].w,h3,l3);
            __nv_bfloat162 t;
            const int off = row*GP + c0 + j*4;
            t.x=h0; t.y=h1; *reinterpret_cast<__nv_bfloat162*>(&Ah[off])   = t;
            t.x=h2; t.y=h3; *reinterpret_cast<__nv_bfloat162*>(&Ah[off+2]) = t;
            t.x=l0; t.y=l1; *reinterpret_cast<__nv_bfloat162*>(&Al[off])   = t;
            t.x=l2; t.y=l3; *reinterpret_cast<__nv_bfloat162*>(&Al[off+2]) = t;
            split2(rb[j].x,h0,l0); split2(rb[j].y,h1,l1);
            split2(rb[j].z,h2,l2); split2(rb[j].w,h3,l3);
            t.x=h0; t.y=h1; *reinterpret_cast<__nv_bfloat162*>(&Bh[off])   = t;
            t.x=h2; t.y=h3; *reinterpret_cast<__nv_bfloat162*>(&Bh[off+2]) = t;
            t.x=l0; t.y=l1; *reinterpret_cast<__nv_bfloat162*>(&Bl[off])   = t;
            t.x=l2; t.y=l3; *reinterpret_cast<__nv_bfloat162*>(&Bl[off+2]) = t;
        }
        __syncthreads();

        if (s < D_MODEL/32 - 1) {   // prefetch next slab (LDG latency hidden by MMA)
            #pragma unroll
            for (int j = 0; j < 4; j++) {
                ra[j] = *reinterpret_cast<const float4*>(Ar + (s+1)*32 + j*4);
                rb[j] = *reinterpret_cast<const float4*>(Br + (s+1)*32 + j*4);
            }
        }

        #pragma unroll
        for (int kk = 0; kk < 32; kk += 16) {
            wmma::fragment<wmma::matrix_a,16,16,16,__nv_bfloat16,wmma::row_major> ah[2], al[2];
            wmma::fragment<wmma::matrix_b,16,16,16,__nv_bfloat16,wmma::col_major> bh[4], bl[4];
            #pragma unroll
            for (int mi = 0; mi < 2; mi++) {
                wmma::load_matrix_sync(ah[mi], Ah + (mw*32 + mi*16)*GP + kk, GP);
                wmma::load_matrix_sync(al[mi], Al + (mw*32 + mi*16)*GP + kk, GP);
            }
            #pragma unroll
            for (int ni = 0; ni < 4; ni++) {
                wmma::load_matrix_sync(bh[ni], Bh + (nw*64 + ni*16)*GP + kk, GP);
                wmma::load_matrix_sync(bl[ni], Bl + (nw*64 + ni*16)*GP + kk, GP);
            }
            #pragma unroll
            for (int mi = 0; mi < 2; mi++)
                #pragma unroll
                for (int ni = 0; ni < 4; ni++) {
                    wmma::mma_sync(acc[mi][ni], ah[mi], bh[ni], acc[mi][ni]);
                    wmma::mma_sync(acc[mi][ni], ah[mi], bl[ni], acc[mi][ni]);
                    wmma::mma_sync(acc[mi][ni], al[mi], bh[ni], acc[mi][ni]);
                }
        }
    }

    __syncthreads();   // all MMA operand reads done before Csm overwrites stages
    #pragma unroll
    for (int mi = 0; mi < 2; mi++)
        #pragma unroll
        for (int ni = 0; ni < 4; ni++)
            wmma::store_matrix_sync(&Csm[(mw*32 + mi*16)*CP + nw*64 + ni*16],
                                    acc[mi][ni], CP, wmma::mem_row_major);
    __syncthreads();

    // writeback: thread -> row (tid>>1), 64-col half (tid&1)
    {
        const int ccol = (tid & 1) * 64;
        const float* src = &Csm[row*CP + ccol];
        float* dst;
        if (SPLIT_HEADS) {
            const int ncol0 = n0 + ccol;            // 64-aligned: exactly one head
            const int h_ = ncol0 / HDIM;
            const int m  = m0 + row;
            const int b_ = m >> 11;
            const int s_ = m & (SEQ - 1);
            dst = out + (((size_t)(b_*NHEADS + h_) * SEQ + s_) * HDIM);
        } else {
            dst = out + (size_t)(m0 + row) * D_MODEL + n0 + ccol;
        }
        #pragma unroll
        for (int c = 0; c < 64; c += 4) {
            float4 o;
            o.x = src[c+0] + bias_s[ccol+c+0];
            o.y = src[c+1] + bias_s[ccol+c+1];
            o.z = src[c+2] + bias_s[ccol+c+2];
            o.w = src[c+3] + bias_s[ccol+c+3];
            *reinterpret_cast<float4*>(dst + c) = o;
        }
    }
}

__global__ __launch_bounds__(256, 1) void qkv_proj_kernel(
    const float* __restrict__ q, const float* __restrict__ k, const float* __restrict__ v,
    const float* __restrict__ Wq, const float* __restrict__ bq,
    const float* __restrict__ Wk, const float* __restrict__ bk,
    const float* __restrict__ Wv, const float* __restrict__ bv)
{
    if (blockIdx.z == 0)      gemm_wmma_body<true>(q, Wq, bq, g_q);
    else if (blockIdx.z == 1) gemm_wmma_body<true>(k, Wk, bk, g_k);
    else                      gemm_wmma_body<true>(v, Wv, bv, g_v);
}

__global__ __launch_bounds__(256, 1) void out_proj_kernel(
    const float* __restrict__ Wo, const float* __restrict__ bo, float* __restrict__ out)
{
    gemm_wmma_body<false>(g_attn, Wo, bo, out);
}

// =====================================================================
// Flash attention with wmma bf16-split.
// Block: 128 q-rows x one (b,h). 8 warps; warp w owns q-rows 16w..16w+15.
// 64-key tiles; S and O tiles live in smem; softmax SIMT (2 threads/row).
// =====================================================================
#define PB 80    // bf16 pitch (160B, mult of 16 elements)
#define PF 68    // f32 pitch (272B, mult of 4 elements)
#define OFF_QH 0
#define OFF_QL (OFF_QH + 128*PB*2)
#define OFF_KH (OFF_QL + 128*PB*2)
#define OFF_KL (OFF_KH + 64*PB*2)
#define OFF_VH (OFF_KL + 64*PB*2)
#define OFF_VL (OFF_VH + 64*PB*2)
#define OFF_PH (OFF_VL + 64*PB*2)
#define OFF_PL (OFF_PH + 128*PB*2)
#define OFF_SF (OFF_PL + 128*PB*2)
#define OFF_OF (OFF_SF + 128*PF*4)
#define ATTN_SMEM (OFF_OF + 128*PF*4)   // 188416 B

__global__ __launch_bounds__(256, 1) void flash_attn_wmma()
{
    extern __shared__ __align__(128) char smem[];
    __nv_bfloat16* Qh = reinterpret_cast<__nv_bfloat16*>(smem + OFF_QH);
    __nv_bfloat16* Ql = reinterpret_cast<__nv_bfloat16*>(smem + OFF_QL);
    __nv_bfloat16* Kh = reinterpret_cast<__nv_bfloat16*>(smem + OFF_KH);
    __nv_bfloat16* Kl = reinterpret_cast<__nv_bfloat16*>(smem + OFF_KL);
    __nv_bfloat16* Vh = reinterpret_cast<__nv_bfloat16*>(smem + OFF_VH);
    __nv_bfloat16* Vl = reinterpret_cast<__nv_bfloat16*>(smem + OFF_VL);
    __nv_bfloat16* Ph = reinterpret_cast<__nv_bfloat16*>(smem + OFF_PH);
    __nv_bfloat16* Pl = reinterpret_cast<__nv_bfloat16*>(smem + OFF_PL);
    float* Sf = reinterpret_cast<float*>(smem + OFF_SF);
    float* Of = reinterpret_cast<float*>(smem + OFF_OF);

    const int tid = threadIdx.x;
    const int wid = tid >> 5;
    const int q0  = blockIdx.x * 128;
    const int bh  = blockIdx.y;

    const int rowQ = tid >> 1;           // 0..127 (softmax/O-update ownership)
    const int cs   = (tid & 1) * 32;     // column half

    const float* qb  = g_q + ((size_t)bh * SEQ + q0) * HDIM;
    const float* kb0 = g_k + (size_t)bh * SEQ * HDIM;
    const float* vb0 = g_v + (size_t)bh * SEQ * HDIM;

    // load + split Q (128x64)
    #pragma unroll
    for (int j = 0; j < 8; j++) {
        float4 qv = *reinterpret_cast<const float4*>(qb + (size_t)rowQ*HDIM + cs + j*4);
        __nv_bfloat16 h0,h1,h2,h3,l0,l1,l2,l3;
        split2(qv.x,h0,l0); split2(qv.y,h1,l1); split2(qv.z,h2,l2); split2(qv.w,h3,l3);
        const int off = rowQ*PB + cs + j*4;
        __nv_bfloat162 t;
        t.x=h0; t.y=h1; *reinterpret_cast<__nv_bfloat162*>(&Qh[off])   = t;
        t.x=h2; t.y=h3; *reinterpret_cast<__nv_bfloat162*>(&Qh[off+2]) = t;
        t.x=l0; t.y=l1; *reinterpret_cast<__nv_bfloat162*>(&Ql[off])   = t;
        t.x=l2; t.y=l3; *reinterpret_cast<__nv_bfloat162*>(&Ql[off+2]) = t;
    }
    for (int i = tid; i < 128*PF; i += 256) Of[i] = 0.f;

    float mrow = -1e30f, lrow = 0.f, alphaR = 1.f;

    for (int kt = 0; kt < SEQ/64; kt++) {
        // load + split K,V tile (64x64 each)
        {
            const int rk = tid >> 2;            // 0..63
            const int ck = (tid & 3) * 16;      // float offset
            const float* kb = kb0 + (size_t)(kt*64 + rk) * HDIM + ck;
            const float* vb = vb0 + (size_t)(kt*64 + rk) * HDIM + ck;
            #pragma unroll
            for (int j = 0; j < 4; j++) {
                float4 kv = *reinterpret_cast<const float4*>(kb + j*4);
                float4 vv = *reinterpret_cast<const float4*>(vb + j*4);
                __nv_bfloat16 h0,h1,h2,h3,l0,l1,l2,l3;
                const int off = rk*PB + ck + j*4;
                __nv_bfloat162 t;
                split2(kv.x,h0,l0); split2(kv.y,h1,l1); split2(kv.z,h2,l2); split2(kv.w,h3,l3);
                t.x=h0; t.y=h1; *reinterpret_cast<__nv_bfloat162*>(&Kh[off])   = t;
                t.x=h2; t.y=h3; *reinterpret_cast<__nv_bfloat162*>(&Kh[off+2]) = t;
                t.x=l0; t.y=l1; *reinterpret_cast<__nv_bfloat162*>(&Kl[off])   = t;
                t.x=l2; t.y=l3; *reinterpret_cast<__nv_bfloat162*>(&Kl[off+2]) = t;
                split2(vv.x,h0,l0); split2(vv.y,h1,l1); split2(vv.z,h2,l2); split2(vv.w,h3,l3);
                t.x=h0; t.y=h1; *reinterpret_cast<__nv_bfloat162*>(&Vh[off])   = t;
                t.x=h2; t.y=h3; *reinterpret_cast<__nv_bfloat162*>(&Vh[off+2]) = t;
                t.x=l0; t.y=l1; *reinterpret_cast<__nv_bfloat162*>(&Vl[off])   = t;
                t.x=l2; t.y=l3; *reinterpret_cast<__nv_bfloat162*>(&Vl[off+2]) = t;
            }
        }
        __syncthreads();   // K/V (and Q on iter 0) visible; prev O-update done

        // ---- S = Q K^T  (warp w: rows 16w..16w+15, all 64 keys) ----
        {
            wmma::fragment<wmma::accumulator,16,16,16,float> sfr[4];
            #pragma unroll
            for (int ni = 0; ni < 4; ni++) wmma::fill_fragment(sfr[ni], 0.f);
            #pragma unroll
            for (int kk = 0; kk < 64; kk += 16) {
                wmma::fragment<wmma::matrix_a,16,16,16,__nv_bfloat16,wmma::row_major> ah, al;
                wmma::load_matrix_sync(ah, Qh + (wid*16)*PB + kk, PB);
                wmma::load_matrix_sync(al, Ql + (wid*16)*PB + kk, PB);
                #pragma unroll
                for (int ni = 0; ni < 4; ni++) {
                    wmma::fragment<wmma::matrix_b,16,16,16,__nv_bfloat16,wmma::col_major> bh, bl;
                    wmma::load_matrix_sync(bh, Kh + (ni*16)*PB + kk, PB);
                    wmma::load_matrix_sync(bl, Kl + (ni*16)*PB + kk, PB);
                    wmma::mma_sync(sfr[ni], ah, bh, sfr[ni]);
                    wmma::mma_sync(sfr[ni], ah, bl, sfr[ni]);
                    wmma::mma_sync(sfr[ni], al, bh, sfr[ni]);
                }
            }
            #pragma unroll
            for (int ni = 0; ni < 4; ni++)
                wmma::store_matrix_sync(&Sf[(wid*16)*PF + ni*16], sfr[ni], PF, wmma::mem_row_major);
        }
        __syncthreads();

        // ---- online softmax (2 threads per row, shfl-paired) ----
        {
            const float* srow = Sf + rowQ*PF + cs;
            float mx = -1e30f;
            #pragma unroll
            for (int c = 0; c < 32; c++) mx = fmaxf(mx, srow[c]);
            mx = fmaxf(mx, __shfl_xor_sync(0xffffffffu, mx, 1));
            const float mnew = fmaxf(mrow, mx * SCALE);
            const float alpha = __expf(mrow - mnew);
            float sum = 0.f;
            #pragma unroll
            for (int c = 0; c < 32; c++) {
                const float p = __expf(srow[c] * SCALE - mnew);
                sum += p;
                __nv_bfloat16 h, l;
                split2(p, h, l);
                Ph[rowQ*PB + cs + c] = h;
                Pl[rowQ*PB + cs + c] = l;
            }
            sum += __shfl_xor_sync(0xffffffffu, sum, 1);
            lrow = lrow * alpha + sum;
            mrow = mnew;
            alphaR = alpha;
        }
        __syncthreads();

        // ---- PV (into Sf, reused) ----
        {
            wmma::fragment<wmma::accumulator,16,16,16,float> ofr[4];
            #pragma unroll
            for (int ni = 0; ni < 4; ni++) wmma::fill_fragment(ofr[ni], 0.f);
            #pragma unroll
            for (int kk = 0; kk < 64; kk += 16) {
                wmma::fragment<wmma::matrix_a,16,16,16,__nv_bfloat16,wmma::row_major> ah, al;
                wmma::load_matrix_sync(ah, Ph + (wid*16)*PB + kk, PB);
                wmma::load_matrix_sync(al, Pl + (wid*16)*PB + kk, PB);
                #pragma unroll
                for (int ni = 0; ni < 4; ni++) {
                    wmma::fragment<wmma::matrix_b,16,16,16,__nv_bfloat16,wmma::row_major> bh, bl;
                    wmma::load_matrix_sync(bh, Vh + kk*PB + ni*16, PB);
                    wmma::load_matrix_sync(bl, Vl + kk*PB + ni*16, PB);
                    wmma::mma_sync(ofr[ni], ah, bh, ofr[ni]);
                    wmma::mma_sync(ofr[ni], ah, bl, ofr[ni]);
                    wmma::mma_sync(ofr[ni], al, bh, ofr[ni]);
                }
            }
            #pragma unroll
            for (int ni = 0; ni < 4; ni++)
                wmma::store_matrix_sync(&Sf[(wid*16)*PF + ni*16], ofr[ni], PF, wmma::mem_row_major);
        }
        __syncthreads();

        // ---- O = O*alpha + PV ----
        {
            float* o = Of + rowQ*PF + cs;
            const float* p = Sf + rowQ*PF + cs;
            #pragma unroll
            for (int c = 0; c < 32; c += 4) {
                float4 ov = *reinterpret_cast<const float4*>(o + c);
                float4 pv = *reinterpret_cast<const float4*>(p + c);
                ov.x = ov.x*alphaR + pv.x;
                ov.y = ov.y*alphaR + pv.y;
                ov.z = ov.z*alphaR + pv.z;
                ov.w = ov.w*alphaR + pv.w;
                *reinterpret_cast<float4*>(o + c) = ov;
            }
        }
        // next loop's K/V STS touches different buffers; loop-top sync protects Sf
    }

    // writeback (same thread->row/half mapping as O-update: no sync needed)
    {
        const int b_ = bh / NHEADS;
        const int h_ = bh % NHEADS;
        const float inv = 1.0f / lrow;
        const float* o = Of + rowQ*PF + cs;
        float* dst = g_attn + ((size_t)(b_*SEQ + q0 + rowQ)) * D_MODEL + h_*HDIM + cs;
        #pragma unroll
        for (int c = 0; c < 32; c += 4) {
            float4 ov = *reinterpret_cast<const float4*>(o + c);
            *reinterpret_cast<float4*>(dst + c) =
                make_float4(ov.x*inv, ov.y*inv, ov.z*inv, ov.w*inv);
        }
    }
}

// =====================================================================
extern "C" void kernel_launch(void* const* d_in, const int* in_sizes, int n_in,
                              void* d_out, int out_size)
{
    const float* query = (const float*)d_in[0];
    const float* key   = (const float*)d_in[1];
    const float* value = (const float*)d_in[2];
    const float* Wq    = (const float*)d_in[3];
    const float* bq    = (const float*)d_in[4];
    const float* Wk    = (const float*)d_in[5];
    const float* bk    = (const float*)d_in[6];
    const float* Wv    = (const float*)d_in[7];
    const float* bv    = (const float*)d_in[8];
    const float* Wo    = (const float*)d_in[9];
    const float* bo    = (const float*)d_in[10];
    float* out = (float*)d_out;

    cudaFuncSetAttribute(qkv_proj_kernel, cudaFuncAttributeMaxDynamicSharedMemorySize, GEMM_SMEM);
    cudaFuncSetAttribute(out_proj_kernel, cudaFuncAttributeMaxDynamicSharedMemorySize, GEMM_SMEM);
    cudaFuncSetAttribute(flash_attn_wmma, cudaFuncAttributeMaxDynamicSharedMemorySize, ATTN_SMEM);

    dim3 qkv_grid(D_MODEL/128, MTOT/128, 3);   // (8, 32, 3)
    qkv_proj_kernel<<<qkv_grid, 256, GEMM_SMEM>>>(query, key, value, Wq, bq, Wk, bk, Wv, bv);

    dim3 attn_grid(SEQ/128, BATCH*NHEADS);     // (16, 32)
    flash_attn_wmma<<<attn_grid, 256, ATTN_SMEM>>>();

    dim3 oproj_grid(D_MODEL/128, MTOT/128);    // (8, 32)
    out_proj_kernel<<<oproj_grid, 256, GEMM_SMEM>>>(Wo, bo, out);
}

// round 7
// speedup vs baseline: 1.5575x; 1.2332x over previous
#include <cuda_runtime.h>
#include <cuda_bf16.h>
#include <mma.h>
#include <math.h>
#include <stdint.h>

using namespace nvcuda;

#define D_MODEL 1024
#define NHEADS  16
#define HDIM    64
#define BATCH   2
#define SEQ     2048
#define MTOT    (BATCH*SEQ)
#define NELEM_X (MTOT*D_MODEL)      // 4194304
#define NELEM_W (D_MODEL*D_MODEL)   // 1048576

// ---------------- scratch (device globals: no allocation allowed) ----------------
__device__ __nv_bfloat16 g_xqh[NELEM_X], g_xql[NELEM_X];
__device__ __nv_bfloat16 g_xkh[NELEM_X], g_xkl[NELEM_X];
__device__ __nv_bfloat16 g_xvh[NELEM_X], g_xvl[NELEM_X];
__device__ __nv_bfloat16 g_wqh[NELEM_W], g_wql[NELEM_W];
__device__ __nv_bfloat16 g_wkh[NELEM_W], g_wkl[NELEM_W];
__device__ __nv_bfloat16 g_wvh[NELEM_W], g_wvl[NELEM_W];
__device__ __nv_bfloat16 g_woh[NELEM_W], g_wol[NELEM_W];
__device__ __nv_bfloat16 g_qh[NELEM_X],  g_ql[NELEM_X];   // [B,H,S,Hd], pre-scaled x8
__device__ __nv_bfloat16 g_kh[NELEM_X],  g_kl[NELEM_X];   // [B,H,S,Hd]
__device__ __nv_bfloat16 g_vh[NELEM_X],  g_vl[NELEM_X];   // [B,H,S,Hd]
__device__ __nv_bfloat16 g_ah[NELEM_X],  g_al[NELEM_X];   // [B,S,D]

// 2-term bf16 split: x ~= hi + lo, |err| ~ 2^-17 |x|
__device__ __forceinline__ void split2(float x, __nv_bfloat16& h, __nv_bfloat16& l) {
    h = __float2bfloat16(x);
    l = __float2bfloat16(x - __bfloat162float(h));
}

__device__ __forceinline__ uint32_t smem_u32(const void* p) {
    uint32_t a;
    asm("{ .reg .u64 t; cvta.to.shared.u64 t, %1; cvt.u32.u64 %0, t; }" : "=r"(a) : "l"(p));
    return a;
}
__device__ __forceinline__ void cp16(uint32_t dst, const void* src) {
    asm volatile("cp.async.cg.shared.global [%0], [%1], 16;" :: "r"(dst), "l"(src));
}
#define CP_COMMIT() asm volatile("cp.async.commit_group;" ::: "memory")
#define CP_WAIT0()  asm volatile("cp.async.wait_group 0;" ::: "memory")
#define CP_WAIT1()  asm volatile("cp.async.wait_group 1;" ::: "memory")

// =====================================================================
// split kernels: f32 -> (bf16 hi, bf16 lo), vectorized float4
// =====================================================================
__global__ __launch_bounds__(256) void split_kernel(const float* __restrict__ src,
                                                    int which, int n4)
{
    __nv_bfloat16 *h, *l;
    switch (which) {
        case 0: h = g_xqh; l = g_xql; break;
        case 1: h = g_xkh; l = g_xkl; break;
        case 2: h = g_xvh; l = g_xvl; break;
        case 3: h = g_wqh; l = g_wql; break;
        case 4: h = g_wkh; l = g_wkl; break;
        case 5: h = g_wvh; l = g_wvl; break;
        default: h = g_woh; l = g_wol; break;
    }
    const int i = blockIdx.x * 256 + threadIdx.x;
    if (i >= n4) return;
    float4 v = reinterpret_cast<const float4*>(src)[i];
    __nv_bfloat16 h0,h1,h2,h3,l0,l1,l2,l3;
    split2(v.x,h0,l0); split2(v.y,h1,l1); split2(v.z,h2,l2); split2(v.w,h3,l3);
    __nv_bfloat162 t;
    __nv_bfloat162* H = reinterpret_cast<__nv_bfloat162*>(h) + i*2;
    __nv_bfloat162* L = reinterpret_cast<__nv_bfloat162*>(l) + i*2;
    t.x=h0; t.y=h1; H[0]=t;  t.x=h2; t.y=h3; H[1]=t;
    t.x=l0; t.y=l1; L[0]=t;  t.x=l2; t.y=l3; L[1]=t;
}

// =====================================================================
// bf16 GEMM: C[M,N] = (Xh+Xl)[M,K] @ (Wh+Wl)[N,K]^T + bias  (3-pass MMA)
// BM=BN=128, BK=32, 256 threads, 8 warps (4m x 2n), cp.async double-buffer.
// =====================================================================
#define SP 40                    // stage pitch (bf16 elems, 80B rows)
#define MAT_BYTES (128*SP*2)     // 10240
#define STAGE_BYTES (4*MAT_BYTES)// 40960 per buffer
#define CP_ 136                  // f32 epilogue pitch
#define GEMM_SMEM (2*STAGE_BYTES + 512)   // Csm (69632) aliases stage buffers

// OUT_MODE: 0 = split-heads bf16 hi/lo pair,  1 = f32 row-major
template<int OUT_MODE>
__device__ __forceinline__ void gemm_bf16_body(
    const __nv_bfloat16* __restrict__ Xh, const __nv_bfloat16* __restrict__ Xl,
    const __nv_bfloat16* __restrict__ Wh, const __nv_bfloat16* __restrict__ Wl,
    const float* __restrict__ bias,
    __nv_bfloat16* outH, __nv_bfloat16* outL, float* outF, float prescale)
{
    extern __shared__ __align__(128) char smem[];
    const uint32_t sb = smem_u32(smem);
    float* Csm    = reinterpret_cast<float*>(smem);                  // alias
    float* bias_s = reinterpret_cast<float*>(smem + 2*STAGE_BYTES);

    const int tid = threadIdx.x;
    const int wid = tid >> 5;
    const int m0  = blockIdx.y * 128;
    const int n0  = blockIdx.x * 128;
    const int mw  = wid >> 1;
    const int nw  = wid & 1;

    if (tid < 128) bias_s[tid] = bias[n0 + tid];

    wmma::fragment<wmma::accumulator,16,16,16,float> acc[2][4];
    #pragma unroll
    for (int mi = 0; mi < 2; mi++)
        #pragma unroll
        for (int ni = 0; ni < 4; ni++) wmma::fill_fragment(acc[mi][ni], 0.f);

    // issue one k-slab (32 cols) of Ah/Al/Bh/Bl into buffer b
    auto issue = [&](int s, int b) {
        const uint32_t base = sb + (uint32_t)b * STAGE_BYTES;
        #pragma unroll
        for (int mat = 0; mat < 4; mat++) {
            const __nv_bfloat16* g = (mat==0) ? Xh : (mat==1) ? Xl : (mat==2) ? Wh : Wl;
            const int rbase = (mat < 2) ? m0 : n0;
            #pragma unroll
            for (int half = 0; half < 2; half++) {
                const int chunk = half*256 + tid;       // 0..511
                const int row = chunk >> 2, col = chunk & 3;
                cp16(base + (uint32_t)mat*MAT_BYTES + row*(SP*2) + col*16,
                     g + (size_t)(rbase + row) * D_MODEL + s*32 + col*8);
            }
        }
    };

    issue(0, 0); CP_COMMIT();

    for (int s = 0; s < D_MODEL/32; s++) {
        if (s < D_MODEL/32 - 1) { issue(s+1, (s+1)&1); CP_COMMIT(); CP_WAIT1(); }
        else                    { CP_WAIT0(); }
        __syncthreads();   // stage s visible to all warps

        const __nv_bfloat16* buf = reinterpret_cast<const __nv_bfloat16*>(smem + (s&1)*STAGE_BYTES);
        const __nv_bfloat16* sAh = buf;
        const __nv_bfloat16* sAl = buf + 128*SP;
        const __nv_bfloat16* sBh = buf + 2*128*SP;
        const __nv_bfloat16* sBl = buf + 3*128*SP;

        #pragma unroll
        for (int kk = 0; kk < 32; kk += 16) {
            wmma::fragment<wmma::matrix_a,16,16,16,__nv_bfloat16,wmma::row_major> ah[2], al[2];
            wmma::fragment<wmma::matrix_b,16,16,16,__nv_bfloat16,wmma::col_major> bh[4], bl[4];
            #pragma unroll
            for (int mi = 0; mi < 2; mi++) {
                wmma::load_matrix_sync(ah[mi], sAh + (mw*32 + mi*16)*SP + kk, SP);
                wmma::load_matrix_sync(al[mi], sAl + (mw*32 + mi*16)*SP + kk, SP);
            }
            #pragma unroll
            for (int ni = 0; ni < 4; ni++) {
                wmma::load_matrix_sync(bh[ni], sBh + (nw*64 + ni*16)*SP + kk, SP);
                wmma::load_matrix_sync(bl[ni], sBl + (nw*64 + ni*16)*SP + kk, SP);
            }
            #pragma unroll
            for (int mi = 0; mi < 2; mi++)
                #pragma unroll
                for (int ni = 0; ni < 4; ni++) {
                    wmma::mma_sync(acc[mi][ni], ah[mi], bh[ni], acc[mi][ni]);
                    wmma::mma_sync(acc[mi][ni], ah[mi], bl[ni], acc[mi][ni]);
                    wmma::mma_sync(acc[mi][ni], al[mi], bh[ni], acc[mi][ni]);
                }
        }
        __syncthreads();   // all warps done with buf before it is re-issued
    }

    // epilogue via smem
    #pragma unroll
    for (int mi = 0; mi < 2; mi++)
        #pragma unroll
        for (int ni = 0; ni < 4; ni++)
            wmma::store_matrix_sync(&Csm[(mw*32 + mi*16)*CP_ + nw*64 + ni*16],
                                    acc[mi][ni], CP_, wmma::mem_row_major);
    __syncthreads();

    {
        const int row  = tid >> 1;
        const int ccol = (tid & 1) * 64;
        const float* src = &Csm[row*CP_ + ccol];
        if (OUT_MODE == 0) {
            const int h_ = (n0 + ccol) / HDIM;        // 64-aligned: one head
            const int m  = m0 + row;
            const int b_ = m >> 11;
            const int s_ = m & (SEQ - 1);
            const size_t base = ((size_t)(b_*NHEADS + h_) * SEQ + s_) * HDIM;
            #pragma unroll
            for (int c = 0; c < 64; c += 2) {
                float f0 = (src[c]   + bias_s[ccol+c])   * prescale;
                float f1 = (src[c+1] + bias_s[ccol+c+1]) * prescale;
                __nv_bfloat16 h0,h1,l0,l1; split2(f0,h0,l0); split2(f1,h1,l1);
                __nv_bfloat162 t;
                t.x=h0; t.y=h1; *reinterpret_cast<__nv_bfloat162*>(outH + base + c) = t;
                t.x=l0; t.y=l1; *reinterpret_cast<__nv_bfloat162*>(outL + base + c) = t;
            }
        } else {
            float* dst = outF + (size_t)(m0 + row) * D_MODEL + n0 + ccol;
            #pragma unroll
            for (int c = 0; c < 64; c += 4) {
                float4 o;
                o.x = src[c+0] + bias_s[ccol+c+0];
                o.y = src[c+1] + bias_s[ccol+c+1];
                o.z = src[c+2] + bias_s[ccol+c+2];
                o.w = src[c+3] + bias_s[ccol+c+3];
                *reinterpret_cast<float4*>(dst + c) = o;
            }
        }
    }
}

__global__ __launch_bounds__(256, 1) void qkv_proj_kernel(
    const float* __restrict__ bq, const float* __restrict__ bk, const float* __restrict__ bv)
{
    if (blockIdx.z == 0)
        gemm_bf16_body<0>(g_xqh, g_xql, g_wqh, g_wql, bq, g_qh, g_ql, nullptr, 8.0f);
    else if (blockIdx.z == 1)
        gemm_bf16_body<0>(g_xkh, g_xkl, g_wkh, g_wkl, bk, g_kh, g_kl, nullptr, 1.0f);
    else
        gemm_bf16_body<0>(g_xvh, g_xvl, g_wvh, g_wvl, bv, g_vh, g_vl, nullptr, 1.0f);
}

__global__ __launch_bounds__(256, 1) void out_proj_kernel(
    const float* __restrict__ bo, float* __restrict__ out)
{
    gemm_bf16_body<1>(g_ah, g_al, g_woh, g_wol, bo, nullptr, nullptr, out, 1.0f);
}

// =====================================================================
// Flash attention (wmma bf16-split), bf16 operands from gmem.
// Block: 128 q-rows x one (b,h). 8 warps; warp w owns q-rows 16w..16w+15.
// 64-key tiles, cp.async double-buffered K/V. O in registers.
// =====================================================================
#define PB 80    // bf16 smem pitch (160B)
#define PF 68    // f32 smem pitch (272B)
#define KV_MAT_BYTES (64*PB*2)            // 10240
#define KV_STAGE (4*KV_MAT_BYTES)         // 40960 (Kh,Kl,Vh,Vl)
#define OFF_Q  0                          // Qh (20480) + Ql (20480)
#define OFF_KV (OFF_Q + 2*128*PB*2)       // 40960: two buffers
#define OFF_P  (OFF_KV + 2*KV_STAGE)      // 122880: Ph (20480) + Pl (20480)
#define OFF_SF (OFF_P + 2*128*PB*2)       // 163840
#define ATTN_SMEM (OFF_SF + 128*PF*4)     // 198656 B

__global__ __launch_bounds__(256, 1) void flash_attn_wmma()
{
    extern __shared__ __align__(128) char smem[];
    const uint32_t sb = smem_u32(smem);
    __nv_bfloat16* Qh = reinterpret_cast<__nv_bfloat16*>(smem + OFF_Q);
    __nv_bfloat16* Ql = Qh + 128*PB;
    __nv_bfloat16* Ph = reinterpret_cast<__nv_bfloat16*>(smem + OFF_P);
    __nv_bfloat16* Pl = Ph + 128*PB;
    float* Sf = reinterpret_cast<float*>(smem + OFF_SF);

    const int tid = threadIdx.x;
    const int wid = tid >> 5;
    const int q0  = blockIdx.x * 128;
    const int bh  = blockIdx.y;

    const int rowQ = tid >> 1;
    const int cs   = (tid & 1) * 32;

    // ---- load Q tile (already x8-scaled, bf16 hi/lo) ----
    {
        const uint4* sh = reinterpret_cast<const uint4*>(g_qh + ((size_t)bh*SEQ + q0 + rowQ)*HDIM + cs);
        const uint4* sl = reinterpret_cast<const uint4*>(g_ql + ((size_t)bh*SEQ + q0 + rowQ)*HDIM + cs);
        uint4* dh = reinterpret_cast<uint4*>(Qh + rowQ*PB + cs);
        uint4* dl = reinterpret_cast<uint4*>(Ql + rowQ*PB + cs);
        #pragma unroll
        for (int i = 0; i < 4; i++) { dh[i] = sh[i]; dl[i] = sl[i]; }
    }

    auto issueKV = [&](int kt, int b) {
        const uint32_t base = sb + OFF_KV + (uint32_t)b * KV_STAGE;
        #pragma unroll
        for (int mat = 0; mat < 4; mat++) {
            const __nv_bfloat16* g = (mat==0) ? g_kh : (mat==1) ? g_kl : (mat==2) ? g_vh : g_vl;
            #pragma unroll
            for (int half = 0; half < 2; half++) {
                const int chunk = half*256 + tid;        // 0..511
                const int row = chunk >> 3, col = chunk & 7;
                cp16(base + (uint32_t)mat*KV_MAT_BYTES + row*(PB*2) + col*16,
                     g + (size_t)(bh*SEQ + kt*64 + row) * HDIM + col*8);
            }
        }
    };

    float oacc[32];
    #pragma unroll
    for (int c = 0; c < 32; c++) oacc[c] = 0.f;
    float mrow = -1e30f, lrow = 0.f;

    issueKV(0, 0); CP_COMMIT();

    for (int kt = 0; kt < SEQ/64; kt++) {
        if (kt < SEQ/64 - 1) { issueKV(kt+1, (kt+1)&1); CP_COMMIT(); CP_WAIT1(); }
        else                 { CP_WAIT0(); }
        __syncthreads();   // K/V tile (and Q on kt=0) visible

        const __nv_bfloat16* kv = reinterpret_cast<const __nv_bfloat16*>(smem + OFF_KV + (kt&1)*KV_STAGE);
        const __nv_bfloat16* Kh = kv;
        const __nv_bfloat16* Kl = kv + 64*PB;
        const __nv_bfloat16* Vh = kv + 2*64*PB;
        const __nv_bfloat16* Vl = kv + 3*64*PB;

        // ---- S = Q K^T (scores already x8 via Q prescale) ----
        {
            wmma::fragment<wmma::accumulator,16,16,16,float> sfr[4];
            #pragma unroll
            for (int ni = 0; ni < 4; ni++) wmma::fill_fragment(sfr[ni], 0.f);
            #pragma unroll
            for (int kk = 0; kk < 64; kk += 16) {
                wmma::fragment<wmma::matrix_a,16,16,16,__nv_bfloat16,wmma::row_major> ah, al;
                wmma::load_matrix_sync(ah, Qh + (wid*16)*PB + kk, PB);
                wmma::load_matrix_sync(al, Ql + (wid*16)*PB + kk, PB);
                #pragma unroll
                for (int ni = 0; ni < 4; ni++) {
                    wmma::fragment<wmma::matrix_b,16,16,16,__nv_bfloat16,wmma::col_major> bh, bl;
                    wmma::load_matrix_sync(bh, Kh + (ni*16)*PB + kk, PB);
                    wmma::load_matrix_sync(bl, Kl + (ni*16)*PB + kk, PB);
                    wmma::mma_sync(sfr[ni], ah, bh, sfr[ni]);
                    wmma::mma_sync(sfr[ni], ah, bl, sfr[ni]);
                    wmma::mma_sync(sfr[ni], al, bh, sfr[ni]);
                }
            }
            #pragma unroll
            for (int ni = 0; ni < 4; ni++)
                wmma::store_matrix_sync(&Sf[(wid*16)*PF + ni*16], sfr[ni], PF, wmma::mem_row_major);
        }
        __syncthreads();

        // ---- online softmax (2 threads per row) ----
        float alphaR;
        {
            const float* srow = Sf + rowQ*PF + cs;
            float mx = -1e30f;
            #pragma unroll
            for (int c = 0; c < 32; c++) mx = fmaxf(mx, srow[c]);
            mx = fmaxf(mx, __shfl_xor_sync(0xffffffffu, mx, 1));
            const float mnew = fmaxf(mrow, mx);
            const float alpha = __expf(mrow - mnew);
            float sum = 0.f;
            #pragma unroll
            for (int c = 0; c < 32; c++) {
                const float p = __expf(srow[c] - mnew);
                sum += p;
                __nv_bfloat16 h, l;
                split2(p, h, l);
                Ph[rowQ*PB + cs + c] = h;
                Pl[rowQ*PB + cs + c] = l;
            }
            sum += __shfl_xor_sync(0xffffffffu, sum, 1);
            lrow = lrow * alpha + sum;
            mrow = mnew;
            alphaR = alpha;
        }
        __syncthreads();

        // ---- PV (into Sf) ----
        {
            wmma::fragment<wmma::accumulator,16,16,16,float> ofr[4];
            #pragma unroll
            for (int ni = 0; ni < 4; ni++) wmma::fill_fragment(ofr[ni], 0.f);
            #pragma unroll
            for (int kk = 0; kk < 64; kk += 16) {
                wmma::fragment<wmma::matrix_a,16,16,16,__nv_bfloat16,wmma::row_major> ah, al;
                wmma::load_matrix_sync(ah, Ph + (wid*16)*PB + kk, PB);
                wmma::load_matrix_sync(al, Pl + (wid*16)*PB + kk, PB);
                #pragma unroll
                for (int ni = 0; ni < 4; ni++) {
                    wmma::fragment<wmma::matrix_b,16,16,16,__nv_bfloat16,wmma::row_major> bh, bl;
                    wmma::load_matrix_sync(bh, Vh + kk*PB + ni*16, PB);
                    wmma::load_matrix_sync(bl, Vl + kk*PB + ni*16, PB);
                    wmma::mma_sync(ofr[ni], ah, bh, ofr[ni]);
                    wmma::mma_sync(ofr[ni], ah, bl, ofr[ni]);
                    wmma::mma_sync(ofr[ni], al, bh, ofr[ni]);
                }
            }
            #pragma unroll
            for (int ni = 0; ni < 4; ni++)
                wmma::store_matrix_sync(&Sf[(wid*16)*PF + ni*16], ofr[ni], PF, wmma::mem_row_major);
        }
        __syncthreads();   // PV done; Sf ready; buffers free for next issue

        // ---- O = O*alpha + PV (registers) ----
        {
            const float* p = Sf + rowQ*PF + cs;
            #pragma unroll
            for (int c = 0; c < 32; c++) oacc[c] = oacc[c]*alphaR + p[c];
        }
        // next iteration's top barrier orders Sf overwrite vs these reads
    }

    // ---- epilogue: normalize, split, write bf16 hi/lo to [B,S,D] ----
    {
        const int b_ = bh / NHEADS;
        const int h_ = bh % NHEADS;
        const float inv = 1.0f / lrow;
        const size_t base = ((size_t)(b_*SEQ + q0 + rowQ)) * D_MODEL + h_*HDIM + cs;
        #pragma unroll
        for (int c = 0; c < 32; c += 2) {
            __nv_bfloat16 h0,h1,l0,l1;
            split2(oacc[c]*inv,   h0, l0);
            split2(oacc[c+1]*inv, h1, l1);
            __nv_bfloat162 t;
            t.x=h0; t.y=h1; *reinterpret_cast<__nv_bfloat162*>(g_ah + base + c) = t;
            t.x=l0; t.y=l1; *reinterpret_cast<__nv_bfloat162*>(g_al + base + c) = t;
        }
    }
}

// =====================================================================
extern "C" void kernel_launch(void* const* d_in, const int* in_sizes, int n_in,
                              void* d_out, int out_size)
{
    const float* query = (const float*)d_in[0];
    const float* key   = (const float*)d_in[1];
    const float* value = (const float*)d_in[2];
    const float* Wq    = (const float*)d_in[3];
    const float* bq    = (const float*)d_in[4];
    const float* Wk    = (const float*)d_in[5];
    const float* bk    = (const float*)d_in[6];
    const float* Wv    = (const float*)d_in[7];
    const float* bv    = (const float*)d_in[8];
    const float* Wo    = (const float*)d_in[9];
    const float* bo    = (const float*)d_in[10];
    float* out = (float*)d_out;

    cudaFuncSetAttribute(qkv_proj_kernel, cudaFuncAttributeMaxDynamicSharedMemorySize, GEMM_SMEM);
    cudaFuncSetAttribute(out_proj_kernel, cudaFuncAttributeMaxDynamicSharedMemorySize, GEMM_SMEM);
    cudaFuncSetAttribute(flash_attn_wmma, cudaFuncAttributeMaxDynamicSharedMemorySize, ATTN_SMEM);

    // pre-split inputs + weights into bf16 hi/lo
    split_kernel<<<NELEM_X/4/256, 256>>>(query, 0, NELEM_X/4);
    split_kernel<<<NELEM_X/4/256, 256>>>(key,   1, NELEM_X/4);
    split_kernel<<<NELEM_X/4/256, 256>>>(value, 2, NELEM_X/4);
    split_kernel<<<NELEM_W/4/256, 256>>>(Wq, 3, NELEM_W/4);
    split_kernel<<<NELEM_W/4/256, 256>>>(Wk, 4, NELEM_W/4);
    split_kernel<<<NELEM_W/4/256, 256>>>(Wv, 5, NELEM_W/4);
    split_kernel<<<NELEM_W/4/256, 256>>>(Wo, 6, NELEM_W/4);

    dim3 qkv_grid(D_MODEL/128, MTOT/128, 3);   // (8, 32, 3)
    qkv_proj_kernel<<<qkv_grid, 256, GEMM_SMEM>>>(bq, bk, bv);

    dim3 attn_grid(SEQ/128, BATCH*NHEADS);     // (16, 32)
    flash_attn_wmma<<<attn_grid, 256, ATTN_SMEM>>>();

    dim3 oproj_grid(D_MODEL/128, MTOT/128);    // (8, 32)
    out_proj_kernel<<<oproj_grid, 256, GEMM_SMEM>>>(bo, out);
}

// round 8
// speedup vs baseline: 1.8000x; 1.1557x over previous
#include <cuda_runtime.h>
#include <cuda_bf16.h>
#include <mma.h>
#include <math.h>
#include <stdint.h>

using namespace nvcuda;

#define D_MODEL 1024
#define NHEADS  16
#define HDIM    64
#define BATCH   2
#define SEQ     2048
#define MTOT    (BATCH*SEQ)
#define NELEM_X (MTOT*D_MODEL)      // 4194304
#define NELEM_W (D_MODEL*D_MODEL)   // 1048576

// ---------------- scratch (device globals: no allocation allowed) ----------------
__device__ __nv_bfloat16 g_xqh[NELEM_X], g_xql[NELEM_X];
__device__ __nv_bfloat16 g_xkh[NELEM_X], g_xkl[NELEM_X];
__device__ __nv_bfloat16 g_xvh[NELEM_X], g_xvl[NELEM_X];
__device__ __nv_bfloat16 g_wqh[NELEM_W], g_wql[NELEM_W];
__device__ __nv_bfloat16 g_wkh[NELEM_W], g_wkl[NELEM_W];
__device__ __nv_bfloat16 g_wvh[NELEM_W], g_wvl[NELEM_W];
__device__ __nv_bfloat16 g_woh[NELEM_W], g_wol[NELEM_W];
__device__ __nv_bfloat16 g_qh[NELEM_X],  g_ql[NELEM_X];   // [B,H,S,Hd], pre-scaled x8
__device__ __nv_bfloat16 g_kh[NELEM_X],  g_kl[NELEM_X];   // [B,H,S,Hd]
__device__ __nv_bfloat16 g_vh[NELEM_X],  g_vl[NELEM_X];   // [B,H,S,Hd]
__device__ __nv_bfloat16 g_ah[NELEM_X],  g_al[NELEM_X];   // [B,S,D]

// 2-term bf16 split: x ~= hi + lo, |err| ~ 2^-17 |x|
__device__ __forceinline__ void split2(float x, __nv_bfloat16& h, __nv_bfloat16& l) {
    h = __float2bfloat16(x);
    l = __float2bfloat16(x - __bfloat162float(h));
}

__device__ __forceinline__ uint32_t smem_u32(const void* p) {
    uint32_t a;
    asm("{ .reg .u64 t; cvta.to.shared.u64 t, %1; cvt.u32.u64 %0, t; }" : "=r"(a) : "l"(p));
    return a;
}
__device__ __forceinline__ void cp16(uint32_t dst, const void* src) {
    asm volatile("cp.async.cg.shared.global [%0], [%1], 16;" :: "r"(dst), "l"(src));
}
#define CP_COMMIT() asm volatile("cp.async.commit_group;" ::: "memory")
#define CP_WAIT0()  asm volatile("cp.async.wait_group 0;" ::: "memory")
#define CP_WAIT1()  asm volatile("cp.async.wait_group 1;" ::: "memory")

// =====================================================================
// split kernels: f32 -> (bf16 hi, bf16 lo), vectorized float4
// =====================================================================
__global__ __launch_bounds__(256) void split_kernel(const float* __restrict__ src,
                                                    int which, int n4)
{
    __nv_bfloat16 *h, *l;
    switch (which) {
        case 0: h = g_xqh; l = g_xql; break;
        case 1: h = g_xkh; l = g_xkl; break;
        case 2: h = g_xvh; l = g_xvl; break;
        case 3: h = g_wqh; l = g_wql; break;
        case 4: h = g_wkh; l = g_wkl; break;
        case 5: h = g_wvh; l = g_wvl; break;
        default: h = g_woh; l = g_wol; break;
    }
    const int i = blockIdx.x * 256 + threadIdx.x;
    if (i >= n4) return;
    float4 v = reinterpret_cast<const float4*>(src)[i];
    __nv_bfloat16 h0,h1,h2,h3,l0,l1,l2,l3;
    split2(v.x,h0,l0); split2(v.y,h1,l1); split2(v.z,h2,l2); split2(v.w,h3,l3);
    __nv_bfloat162 t;
    __nv_bfloat162* H = reinterpret_cast<__nv_bfloat162*>(h) + i*2;
    __nv_bfloat162* L = reinterpret_cast<__nv_bfloat162*>(l) + i*2;
    t.x=h0; t.y=h1; H[0]=t;  t.x=h2; t.y=h3; H[1]=t;
    t.x=l0; t.y=l1; L[0]=t;  t.x=l2; t.y=l3; L[1]=t;
}

// =====================================================================
// bf16 GEMM: C[M,N] = (Xh+Xl)[M,K] @ (Wh+Wl)[N,K]^T + bias  (3-pass MMA)
// BM=BN=128, BK=32, 256 threads, 8 warps (4m x 2n), cp.async double-buffer.
// =====================================================================
#define SP 40                    // stage pitch (bf16 elems, 80B rows)
#define MAT_BYTES (128*SP*2)     // 10240
#define STAGE_BYTES (4*MAT_BYTES)// 40960 per buffer
#define CP_ 136                  // f32 epilogue pitch
#define GEMM_SMEM (2*STAGE_BYTES + 512)   // Csm (69632) aliases stage buffers

// OUT_MODE: 0 = split-heads bf16 hi/lo pair,  1 = f32 row-major
template<int OUT_MODE>
__device__ __forceinline__ void gemm_bf16_body(
    const __nv_bfloat16* __restrict__ Xh, const __nv_bfloat16* __restrict__ Xl,
    const __nv_bfloat16* __restrict__ Wh, const __nv_bfloat16* __restrict__ Wl,
    const float* __restrict__ bias,
    __nv_bfloat16* outH, __nv_bfloat16* outL, float* outF, float prescale)
{
    extern __shared__ __align__(128) char smem[];
    const uint32_t sb = smem_u32(smem);
    float* Csm    = reinterpret_cast<float*>(smem);                  // alias
    float* bias_s = reinterpret_cast<float*>(smem + 2*STAGE_BYTES);

    const int tid = threadIdx.x;
    const int wid = tid >> 5;
    const int m0  = blockIdx.y * 128;
    const int n0  = blockIdx.x * 128;
    const int mw  = wid >> 1;
    const int nw  = wid & 1;

    if (tid < 128) bias_s[tid] = bias[n0 + tid];

    wmma::fragment<wmma::accumulator,16,16,16,float> acc[2][4];
    #pragma unroll
    for (int mi = 0; mi < 2; mi++)
        #pragma unroll
        for (int ni = 0; ni < 4; ni++) wmma::fill_fragment(acc[mi][ni], 0.f);

    auto issue = [&](int s, int b) {
        const uint32_t base = sb + (uint32_t)b * STAGE_BYTES;
        #pragma unroll
        for (int mat = 0; mat < 4; mat++) {
            const __nv_bfloat16* g = (mat==0) ? Xh : (mat==1) ? Xl : (mat==2) ? Wh : Wl;
            const int rbase = (mat < 2) ? m0 : n0;
            #pragma unroll
            for (int half = 0; half < 2; half++) {
                const int chunk = half*256 + tid;       // 0..511
                const int row = chunk >> 2, col = chunk & 3;
                cp16(base + (uint32_t)mat*MAT_BYTES + row*(SP*2) + col*16,
                     g + (size_t)(rbase + row) * D_MODEL + s*32 + col*8);
            }
        }
    };

    issue(0, 0); CP_COMMIT();

    for (int s = 0; s < D_MODEL/32; s++) {
        if (s < D_MODEL/32 - 1) { issue(s+1, (s+1)&1); CP_COMMIT(); CP_WAIT1(); }
        else                    { CP_WAIT0(); }
        __syncthreads();   // stage s visible to all warps

        const __nv_bfloat16* buf = reinterpret_cast<const __nv_bfloat16*>(smem + (s&1)*STAGE_BYTES);
        const __nv_bfloat16* sAh = buf;
        const __nv_bfloat16* sAl = buf + 128*SP;
        const __nv_bfloat16* sBh = buf + 2*128*SP;
        const __nv_bfloat16* sBl = buf + 3*128*SP;

        #pragma unroll
        for (int kk = 0; kk < 32; kk += 16) {
            wmma::fragment<wmma::matrix_a,16,16,16,__nv_bfloat16,wmma::row_major> ah[2], al[2];
            wmma::fragment<wmma::matrix_b,16,16,16,__nv_bfloat16,wmma::col_major> bh[4], bl[4];
            #pragma unroll
            for (int mi = 0; mi < 2; mi++) {
                wmma::load_matrix_sync(ah[mi], sAh + (mw*32 + mi*16)*SP + kk, SP);
                wmma::load_matrix_sync(al[mi], sAl + (mw*32 + mi*16)*SP + kk, SP);
            }
            #pragma unroll
            for (int ni = 0; ni < 4; ni++) {
                wmma::load_matrix_sync(bh[ni], sBh + (nw*64 + ni*16)*SP + kk, SP);
                wmma::load_matrix_sync(bl[ni], sBl + (nw*64 + ni*16)*SP + kk, SP);
            }
            #pragma unroll
            for (int mi = 0; mi < 2; mi++)
                #pragma unroll
                for (int ni = 0; ni < 4; ni++) {
                    wmma::mma_sync(acc[mi][ni], ah[mi], bh[ni], acc[mi][ni]);
                    wmma::mma_sync(acc[mi][ni], ah[mi], bl[ni], acc[mi][ni]);
                    wmma::mma_sync(acc[mi][ni], al[mi], bh[ni], acc[mi][ni]);
                }
        }
        __syncthreads();   // all warps done with buf before it is re-issued
    }

    // epilogue via smem
    #pragma unroll
    for (int mi = 0; mi < 2; mi++)
        #pragma unroll
        for (int ni = 0; ni < 4; ni++)
            wmma::store_matrix_sync(&Csm[(mw*32 + mi*16)*CP_ + nw*64 + ni*16],
                                    acc[mi][ni], CP_, wmma::mem_row_major);
    __syncthreads();

    {
        const int row  = tid >> 1;
        const int ccol = (tid & 1) * 64;
        const float* src = &Csm[row*CP_ + ccol];
        if (OUT_MODE == 0) {
            const int h_ = (n0 + ccol) / HDIM;        // 64-aligned: one head
            const int m  = m0 + row;
            const int b_ = m >> 11;
            const int s_ = m & (SEQ - 1);
            const size_t base = ((size_t)(b_*NHEADS + h_) * SEQ + s_) * HDIM;
            #pragma unroll
            for (int c = 0; c < 64; c += 2) {
                float f0 = (src[c]   + bias_s[ccol+c])   * prescale;
                float f1 = (src[c+1] + bias_s[ccol+c+1]) * prescale;
                __nv_bfloat16 h0,h1,l0,l1; split2(f0,h0,l0); split2(f1,h1,l1);
                __nv_bfloat162 t;
                t.x=h0; t.y=h1; *reinterpret_cast<__nv_bfloat162*>(outH + base + c) = t;
                t.x=l0; t.y=l1; *reinterpret_cast<__nv_bfloat162*>(outL + base + c) = t;
            }
        } else {
            float* dst = outF + (size_t)(m0 + row) * D_MODEL + n0 + ccol;
            #pragma unroll
            for (int c = 0; c < 64; c += 4) {
                float4 o;
                o.x = src[c+0] + bias_s[ccol+c+0];
                o.y = src[c+1] + bias_s[ccol+c+1];
                o.z = src[c+2] + bias_s[ccol+c+2];
                o.w = src[c+3] + bias_s[ccol+c+3];
                *reinterpret_cast<float4*>(dst + c) = o;
            }
        }
    }
}

__global__ __launch_bounds__(256, 1) void qkv_proj_kernel(
    const float* __restrict__ bq, const float* __restrict__ bk, const float* __restrict__ bv)
{
    if (blockIdx.z == 0)
        gemm_bf16_body<0>(g_xqh, g_xql, g_wqh, g_wql, bq, g_qh, g_ql, nullptr, 8.0f);
    else if (blockIdx.z == 1)
        gemm_bf16_body<0>(g_xkh, g_xkl, g_wkh, g_wkl, bk, g_kh, g_kl, nullptr, 1.0f);
    else
        gemm_bf16_body<0>(g_xvh, g_xvl, g_wvh, g_wvl, bv, g_vh, g_vl, nullptr, 1.0f);
}

__global__ __launch_bounds__(256, 1) void out_proj_kernel(
    const float* __restrict__ bo, float* __restrict__ out)
{
    gemm_bf16_body<1>(g_ah, g_al, g_woh, g_wol, bo, nullptr, nullptr, out, 1.0f);
}

// =====================================================================
// Flash attention, warp-autonomous: each warp owns 16 q-rows and runs its
// private S -> softmax -> PV chain (only __syncwarp). ONE __syncthreads
// per k-tile (K/V staging). K/V: 3-deep cp.async ring.
// =====================================================================
#define PB 72    // bf16 smem pitch (144B, mult of 8 elems)
#define PF 68    // f32 smem pitch (272B)
#define KV_MAT (64*PB*2)                  // 9216
#define KV_STAGE (4*KV_MAT)               // 36864 (Kh,Kl,Vh,Vl)
#define OFF_Q  0                          // Qh+Ql: 36864
#define OFF_KV (OFF_Q + 2*128*PB*2)       // 3 stages: 110592
#define OFF_P  (OFF_KV + 3*KV_STAGE)      // Ph+Pl: 36864
#define OFF_SF (OFF_P + 2*128*PB*2)       // Sf: 34816
#define ATTN_SMEM (OFF_SF + 128*PF*4)     // 219136 B

__global__ __launch_bounds__(256, 1) void flash_attn_wmma()
{
    extern __shared__ __align__(128) char smem[];
    const uint32_t sb = smem_u32(smem);
    __nv_bfloat16* Qh = reinterpret_cast<__nv_bfloat16*>(smem + OFF_Q);
    __nv_bfloat16* Ql = Qh + 128*PB;
    __nv_bfloat16* Ph = reinterpret_cast<__nv_bfloat16*>(smem + OFF_P);
    __nv_bfloat16* Pl = Ph + 128*PB;
    float* Sf = reinterpret_cast<float*>(smem + OFF_SF);

    const int tid  = threadIdx.x;
    const int wid  = tid >> 5;
    const int lane = tid & 31;
    const int q0   = blockIdx.x * 128;
    const int bh   = blockIdx.y;

    const int rowQ = wid*16 + (lane >> 1);   // warp-local row ownership
    const int cs   = (lane & 1) * 32;

    // ---- load Q tile (x8-scaled bf16 hi/lo); row tid>>1 == warp-local ----
    {
        const int r = tid >> 1;
        const int ch = (tid & 1) * 32;
        const uint4* shp = reinterpret_cast<const uint4*>(g_qh + ((size_t)bh*SEQ + q0 + r)*HDIM + ch);
        const uint4* slp = reinterpret_cast<const uint4*>(g_ql + ((size_t)bh*SEQ + q0 + r)*HDIM + ch);
        uint4* dh = reinterpret_cast<uint4*>(Qh + r*PB + ch);
        uint4* dl = reinterpret_cast<uint4*>(Ql + r*PB + ch);
        #pragma unroll
        for (int i = 0; i < 4; i++) { dh[i] = shp[i]; dl[i] = slp[i]; }
    }

    auto issueKV = [&](int kt, int b) {
        const uint32_t base = sb + OFF_KV + (uint32_t)b * KV_STAGE;
        #pragma unroll
        for (int mat = 0; mat < 4; mat++) {
            const __nv_bfloat16* g = (mat==0) ? g_kh : (mat==1) ? g_kl : (mat==2) ? g_vh : g_vl;
            #pragma unroll
            for (int half = 0; half < 2; half++) {
                const int chunk = half*256 + tid;        // 0..511
                const int row = chunk >> 3, col = chunk & 7;
                cp16(base + (uint32_t)mat*KV_MAT + row*(PB*2) + col*16,
                     g + (size_t)(bh*SEQ + kt*64 + row) * HDIM + col*8);
            }
        }
    };

    float oacc[32];
    #pragma unroll
    for (int c = 0; c < 32; c++) oacc[c] = 0.f;
    float mrow = -1e30f, lrow = 0.f;

    issueKV(0, 0); CP_COMMIT();

    for (int kt = 0; kt < SEQ/64; kt++) {
        if (kt < SEQ/64 - 1) { issueKV(kt+1, (kt+1)%3); CP_COMMIT(); CP_WAIT1(); }
        else                 { CP_WAIT0(); }
        __syncthreads();   // the ONLY block barrier per tile: K/V stage visible
                           // (3-deep ring: buffer reuse is 2 barriers downstream of last read)

        const __nv_bfloat16* kv = reinterpret_cast<const __nv_bfloat16*>(smem + OFF_KV + (kt%3)*KV_STAGE);
        const __nv_bfloat16* Kh = kv;
        const __nv_bfloat16* Kl = kv + 64*PB;
        const __nv_bfloat16* Vh = kv + 2*64*PB;
        const __nv_bfloat16* Vl = kv + 3*64*PB;

        // ---- S = Q K^T (x8 via Q prescale); warp-private rows ----
        {
            wmma::fragment<wmma::accumulator,16,16,16,float> sfr[4];
            #pragma unroll
            for (int ni = 0; ni < 4; ni++) wmma::fill_fragment(sfr[ni], 0.f);
            #pragma unroll
            for (int kk = 0; kk < 64; kk += 16) {
                wmma::fragment<wmma::matrix_a,16,16,16,__nv_bfloat16,wmma::row_major> ah, al;
                wmma::load_matrix_sync(ah, Qh + (wid*16)*PB + kk, PB);
                wmma::load_matrix_sync(al, Ql + (wid*16)*PB + kk, PB);
                #pragma unroll
                for (int ni = 0; ni < 4; ni++) {
                    wmma::fragment<wmma::matrix_b,16,16,16,__nv_bfloat16,wmma::col_major> bh, bl;
                    wmma::load_matrix_sync(bh, Kh + (ni*16)*PB + kk, PB);
                    wmma::load_matrix_sync(bl, Kl + (ni*16)*PB + kk, PB);
                    wmma::mma_sync(sfr[ni], ah, bh, sfr[ni]);
                    wmma::mma_sync(sfr[ni], ah, bl, sfr[ni]);
                    wmma::mma_sync(sfr[ni], al, bh, sfr[ni]);
                }
            }
            #pragma unroll
            for (int ni = 0; ni < 4; ni++)
                wmma::store_matrix_sync(&Sf[(wid*16)*PF + ni*16], sfr[ni], PF, wmma::mem_row_major);
        }
        __syncwarp();

        // ---- softmax on own rows (2 lanes per row) ----
        float alphaR;
        {
            const float* srow = Sf + rowQ*PF + cs;
            float mx = -1e30f;
            #pragma unroll
            for (int c = 0; c < 32; c++) mx = fmaxf(mx, srow[c]);
            mx = fmaxf(mx, __shfl_xor_sync(0xffffffffu, mx, 1));
            const float mnew = fmaxf(mrow, mx);
            const float alpha = __expf(mrow - mnew);
            float sum = 0.f;
            #pragma unroll
            for (int c = 0; c < 32; c++) {
                const float p = __expf(srow[c] - mnew);
                sum += p;
                __nv_bfloat16 h, l;
                split2(p, h, l);
                Ph[rowQ*PB + cs + c] = h;
                Pl[rowQ*PB + cs + c] = l;
            }
            sum += __shfl_xor_sync(0xffffffffu, sum, 1);
            lrow = lrow * alpha + sum;
            mrow = mnew;
            alphaR = alpha;
        }
        __syncwarp();

        // ---- PV on own rows (into Sf, warp-private) ----
        {
            wmma::fragment<wmma::accumulator,16,16,16,float> ofr[4];
            #pragma unroll
            for (int ni = 0; ni < 4; ni++) wmma::fill_fragment(ofr[ni], 0.f);
            #pragma unroll
            for (int kk = 0; kk < 64; kk += 16) {
                wmma::fragment<wmma::matrix_a,16,16,16,__nv_bfloat16,wmma::row_major> ah, al;
                wmma::load_matrix_sync(ah, Ph + (wid*16)*PB + kk, PB);
                wmma::load_matrix_sync(al, Pl + (wid*16)*PB + kk, PB);
                #pragma unroll
                for (int ni = 0; ni < 4; ni++) {
                    wmma::fragment<wmma::matrix_b,16,16,16,__nv_bfloat16,wmma::row_major> bh, bl;
                    wmma::load_matrix_sync(bh, Vh + kk*PB + ni*16, PB);
                    wmma::load_matrix_sync(bl, Vl + kk*PB + ni*16, PB);
                    wmma::mma_sync(ofr[ni], ah, bh, ofr[ni]);
                    wmma::mma_sync(ofr[ni], ah, bl, ofr[ni]);
                    wmma::mma_sync(ofr[ni], al, bh, ofr[ni]);
                }
            }
            #pragma unroll
            for (int ni = 0; ni < 4; ni++)
                wmma::store_matrix_sync(&Sf[(wid*16)*PF + ni*16], ofr[ni], PF, wmma::mem_row_major);
        }
        __syncwarp();

        // ---- O = O*alpha + PV (registers; reads own rows only) ----
        {
            const float* p = Sf + rowQ*PF + cs;
            #pragma unroll
            for (int c = 0; c < 32; c++) oacc[c] = oacc[c]*alphaR + p[c];
        }
        __syncwarp();   // Sf overwrite next tile is warp-local; order reads first
    }

    // ---- epilogue: normalize, split, write bf16 hi/lo to [B,S,D] ----
    {
        const int b_ = bh / NHEADS;
        const int h_ = bh % NHEADS;
        const float inv = 1.0f / lrow;
        const size_t base = ((size_t)(b_*SEQ + q0 + rowQ)) * D_MODEL + h_*HDIM + cs;
        #pragma unroll
        for (int c = 0; c < 32; c += 2) {
            __nv_bfloat16 h0,h1,l0,l1;
            split2(oacc[c]*inv,   h0, l0);
            split2(oacc[c+1]*inv, h1, l1);
            __nv_bfloat162 t;
            t.x=h0; t.y=h1; *reinterpret_cast<__nv_bfloat162*>(g_ah + base + c) = t;
            t.x=l0; t.y=l1; *reinterpret_cast<__nv_bfloat162*>(g_al + base + c) = t;
        }
    }
}

// =====================================================================
extern "C" void kernel_launch(void* const* d_in, const int* in_sizes, int n_in,
                              void* d_out, int out_size)
{
    const float* query = (const float*)d_in[0];
    const float* key   = (const float*)d_in[1];
    const float* value = (const float*)d_in[2];
    const float* Wq    = (const float*)d_in[3];
    const float* bq    = (const float*)d_in[4];
    const float* Wk    = (const float*)d_in[5];
    const float* bk    = (const float*)d_in[6];
    const float* Wv    = (const float*)d_in[7];
    const float* bv    = (const float*)d_in[8];
    const float* Wo    = (const float*)d_in[9];
    const float* bo    = (const float*)d_in[10];
    float* out = (float*)d_out;

    cudaFuncSetAttribute(qkv_proj_kernel, cudaFuncAttributeMaxDynamicSharedMemorySize, GEMM_SMEM);
    cudaFuncSetAttribute(out_proj_kernel, cudaFuncAttributeMaxDynamicSharedMemorySize, GEMM_SMEM);
    cudaFuncSetAttribute(flash_attn_wmma, cudaFuncAttributeMaxDynamicSharedMemorySize, ATTN_SMEM);

    // pre-split inputs + weights into bf16 hi/lo
    split_kernel<<<NELEM_X/4/256, 256>>>(query, 0, NELEM_X/4);
    split_kernel<<<NELEM_X/4/256, 256>>>(key,   1, NELEM_X/4);
    split_kernel<<<NELEM_X/4/256, 256>>>(value, 2, NELEM_X/4);
    split_kernel<<<NELEM_W/4/256, 256>>>(Wq, 3, NELEM_W/4);
    split_kernel<<<NELEM_W/4/256, 256>>>(Wk, 4, NELEM_W/4);
    split_kernel<<<NELEM_W/4/256, 256>>>(Wv, 5, NELEM_W/4);
    split_kernel<<<NELEM_W/4/256, 256>>>(Wo, 6, NELEM_W/4);

    dim3 qkv_grid(D_MODEL/128, MTOT/128, 3);   // (8, 32, 3)
    qkv_proj_kernel<<<qkv_grid, 256, GEMM_SMEM>>>(bq, bk, bv);

    dim3 attn_grid(SEQ/128, BATCH*NHEADS);     // (16, 32)
    flash_attn_wmma<<<attn_grid, 256, ATTN_SMEM>>>();

    dim3 oproj_grid(D_MODEL/128, MTOT/128);    // (8, 32)
    out_proj_kernel<<<oproj_grid, 256, GEMM_SMEM>>>(bo, out);
}

// round 9
// speedup vs baseline: 2.8938x; 1.6077x over previous
#include <cuda_runtime.h>
#include <cuda_bf16.h>
#include <mma.h>
#include <math.h>
#include <stdint.h>

using namespace nvcuda;

#define D_MODEL 1024
#define NHEADS  16
#define HDIM    64
#define BATCH   2
#define SEQ     2048
#define MTOT    (BATCH*SEQ)
#define NELEM_X (MTOT*D_MODEL)      // 4194304
#define NELEM_W (D_MODEL*D_MODEL)   // 1048576

// ---------------- scratch (device globals: no allocation allowed) ----------------
__device__ __nv_bfloat16 g_xqh[NELEM_X], g_xql[NELEM_X];
__device__ __nv_bfloat16 g_xkh[NELEM_X], g_xkl[NELEM_X];
__device__ __nv_bfloat16 g_xvh[NELEM_X], g_xvl[NELEM_X];
__device__ __nv_bfloat16 g_wqh[NELEM_W], g_wql[NELEM_W];
__device__ __nv_bfloat16 g_wkh[NELEM_W], g_wkl[NELEM_W];
__device__ __nv_bfloat16 g_wvh[NELEM_W], g_wvl[NELEM_W];
__device__ __nv_bfloat16 g_woh[NELEM_W], g_wol[NELEM_W];
__device__ __nv_bfloat16 g_qh[NELEM_X],  g_ql[NELEM_X];   // [B,H,S,Hd], pre-scaled x8
__device__ __nv_bfloat16 g_kh[NELEM_X],  g_kl[NELEM_X];   // [B,H,S,Hd]
__device__ __nv_bfloat16 g_vh[NELEM_X],  g_vl[NELEM_X];   // [B,H,S,Hd]
__device__ __nv_bfloat16 g_ah[NELEM_X],  g_al[NELEM_X];   // [B,S,D]

// 2-term bf16 split: x ~= hi + lo, |err| ~ 2^-17 |x|
__device__ __forceinline__ void split2(float x, __nv_bfloat16& h, __nv_bfloat16& l) {
    h = __float2bfloat16(x);
    l = __float2bfloat16(x - __bfloat162float(h));
}

__device__ __forceinline__ uint32_t smem_u32(const void* p) {
    uint32_t a;
    asm("{ .reg .u64 t; cvta.to.shared.u64 t, %1; cvt.u32.u64 %0, t; }" : "=r"(a) : "l"(p));
    return a;
}
__device__ __forceinline__ void cp16(uint32_t dst, const void* src) {
    asm volatile("cp.async.cg.shared.global [%0], [%1], 16;" :: "r"(dst), "l"(src));
}
#define CP_COMMIT() asm volatile("cp.async.commit_group;" ::: "memory")
#define CP_WAIT0()  asm volatile("cp.async.wait_group 0;" ::: "memory")
#define CP_WAIT1()  asm volatile("cp.async.wait_group 1;" ::: "memory")

// ---- raw mma.sync helpers (defined layouts, portable PTX) ----
__device__ __forceinline__ void ldsm4(uint32_t* d, uint32_t a) {
    asm volatile("ldmatrix.sync.aligned.m8n8.x4.shared.b16 {%0,%1,%2,%3}, [%4];"
        : "=r"(d[0]), "=r"(d[1]), "=r"(d[2]), "=r"(d[3]) : "r"(a));
}
__device__ __forceinline__ void ldsm4t(uint32_t* d, uint32_t a) {
    asm volatile("ldmatrix.sync.aligned.m8n8.x4.trans.shared.b16 {%0,%1,%2,%3}, [%4];"
        : "=r"(d[0]), "=r"(d[1]), "=r"(d[2]), "=r"(d[3]) : "r"(a));
}
__device__ __forceinline__ void mma16816(float* c, const uint32_t* a, const uint32_t* b) {
    asm volatile("mma.sync.aligned.m16n8k16.row.col.f32.bf16.bf16.f32 "
        "{%0,%1,%2,%3}, {%4,%5,%6,%7}, {%8,%9}, {%0,%1,%2,%3};"
        : "+f"(c[0]), "+f"(c[1]), "+f"(c[2]), "+f"(c[3])
        : "r"(a[0]), "r"(a[1]), "r"(a[2]), "r"(a[3]), "r"(b[0]), "r"(b[1]));
}
__device__ __forceinline__ uint32_t packbf(__nv_bfloat16 lo, __nv_bfloat16 hi) {
    __nv_bfloat162 t; t.x = lo; t.y = hi;
    return *reinterpret_cast<uint32_t*>(&t);
}

// =====================================================================
// split kernels: f32 -> (bf16 hi, bf16 lo), vectorized float4
// =====================================================================
__global__ __launch_bounds__(256) void split_kernel(const float* __restrict__ src,
                                                    int which, int n4)
{
    __nv_bfloat16 *h, *l;
    switch (which) {
        case 0: h = g_xqh; l = g_xql; break;
        case 1: h = g_xkh; l = g_xkl; break;
        case 2: h = g_xvh; l = g_xvl; break;
        case 3: h = g_wqh; l = g_wql; break;
        case 4: h = g_wkh; l = g_wkl; break;
        case 5: h = g_wvh; l = g_wvl; break;
        default: h = g_woh; l = g_wol; break;
    }
    const int i = blockIdx.x * 256 + threadIdx.x;
    if (i >= n4) return;
    float4 v = reinterpret_cast<const float4*>(src)[i];
    __nv_bfloat16 h0,h1,h2,h3,l0,l1,l2,l3;
    split2(v.x,h0,l0); split2(v.y,h1,l1); split2(v.z,h2,l2); split2(v.w,h3,l3);
    __nv_bfloat162 t;
    __nv_bfloat162* H = reinterpret_cast<__nv_bfloat162*>(h) + i*2;
    __nv_bfloat162* L = reinterpret_cast<__nv_bfloat162*>(l) + i*2;
    t.x=h0; t.y=h1; H[0]=t;  t.x=h2; t.y=h3; H[1]=t;
    t.x=l0; t.y=l1; L[0]=t;  t.x=l2; t.y=l3; L[1]=t;
}

// =====================================================================
// bf16 GEMM (unchanged from round 8): C = (Xh+Xl)(Wh+Wl)^T + bias, 3-pass
// =====================================================================
#define SP 40
#define MAT_BYTES (128*SP*2)
#define STAGE_BYTES (4*MAT_BYTES)
#define CP_ 136
#define GEMM_SMEM (2*STAGE_BYTES + 512)

template<int OUT_MODE>
__device__ __forceinline__ void gemm_bf16_body(
    const __nv_bfloat16* __restrict__ Xh, const __nv_bfloat16* __restrict__ Xl,
    const __nv_bfloat16* __restrict__ Wh, const __nv_bfloat16* __restrict__ Wl,
    const float* __restrict__ bias,
    __nv_bfloat16* outH, __nv_bfloat16* outL, float* outF, float prescale)
{
    extern __shared__ __align__(128) char smem[];
    const uint32_t sb = smem_u32(smem);
    float* Csm    = reinterpret_cast<float*>(smem);
    float* bias_s = reinterpret_cast<float*>(smem + 2*STAGE_BYTES);

    const int tid = threadIdx.x;
    const int wid = tid >> 5;
    const int m0  = blockIdx.y * 128;
    const int n0  = blockIdx.x * 128;
    const int mw  = wid >> 1;
    const int nw  = wid & 1;

    if (tid < 128) bias_s[tid] = bias[n0 + tid];

    wmma::fragment<wmma::accumulator,16,16,16,float> acc[2][4];
    #pragma unroll
    for (int mi = 0; mi < 2; mi++)
        #pragma unroll
        for (int ni = 0; ni < 4; ni++) wmma::fill_fragment(acc[mi][ni], 0.f);

    auto issue = [&](int s, int b) {
        const uint32_t base = sb + (uint32_t)b * STAGE_BYTES;
        #pragma unroll
        for (int mat = 0; mat < 4; mat++) {
            const __nv_bfloat16* g = (mat==0) ? Xh : (mat==1) ? Xl : (mat==2) ? Wh : Wl;
            const int rbase = (mat < 2) ? m0 : n0;
            #pragma unroll
            for (int half = 0; half < 2; half++) {
                const int chunk = half*256 + tid;
                const int row = chunk >> 2, col = chunk & 3;
                cp16(base + (uint32_t)mat*MAT_BYTES + row*(SP*2) + col*16,
                     g + (size_t)(rbase + row) * D_MODEL + s*32 + col*8);
            }
        }
    };

    issue(0, 0); CP_COMMIT();

    for (int s = 0; s < D_MODEL/32; s++) {
        if (s < D_MODEL/32 - 1) { issue(s+1, (s+1)&1); CP_COMMIT(); CP_WAIT1(); }
        else                    { CP_WAIT0(); }
        __syncthreads();

        const __nv_bfloat16* buf = reinterpret_cast<const __nv_bfloat16*>(smem + (s&1)*STAGE_BYTES);
        const __nv_bfloat16* sAh = buf;
        const __nv_bfloat16* sAl = buf + 128*SP;
        const __nv_bfloat16* sBh = buf + 2*128*SP;
        const __nv_bfloat16* sBl = buf + 3*128*SP;

        #pragma unroll
        for (int kk = 0; kk < 32; kk += 16) {
            wmma::fragment<wmma::matrix_a,16,16,16,__nv_bfloat16,wmma::row_major> ah[2], al[2];
            wmma::fragment<wmma::matrix_b,16,16,16,__nv_bfloat16,wmma::col_major> bh[4], bl[4];
            #pragma unroll
            for (int mi = 0; mi < 2; mi++) {
                wmma::load_matrix_sync(ah[mi], sAh + (mw*32 + mi*16)*SP + kk, SP);
                wmma::load_matrix_sync(al[mi], sAl + (mw*32 + mi*16)*SP + kk, SP);
            }
            #pragma unroll
            for (int ni = 0; ni < 4; ni++) {
                wmma::load_matrix_sync(bh[ni], sBh + (nw*64 + ni*16)*SP + kk, SP);
                wmma::load_matrix_sync(bl[ni], sBl + (nw*64 + ni*16)*SP + kk, SP);
            }
            #pragma unroll
            for (int mi = 0; mi < 2; mi++)
                #pragma unroll
                for (int ni = 0; ni < 4; ni++) {
                    wmma::mma_sync(acc[mi][ni], ah[mi], bh[ni], acc[mi][ni]);
                    wmma::mma_sync(acc[mi][ni], ah[mi], bl[ni], acc[mi][ni]);
                    wmma::mma_sync(acc[mi][ni], al[mi], bh[ni], acc[mi][ni]);
                }
        }
        __syncthreads();
    }

    #pragma unroll
    for (int mi = 0; mi < 2; mi++)
        #pragma unroll
        for (int ni = 0; ni < 4; ni++)
            wmma::store_matrix_sync(&Csm[(mw*32 + mi*16)*CP_ + nw*64 + ni*16],
                                    acc[mi][ni], CP_, wmma::mem_row_major);
    __syncthreads();

    {
        const int row  = tid >> 1;
        const int ccol = (tid & 1) * 64;
        const float* src = &Csm[row*CP_ + ccol];
        if (OUT_MODE == 0) {
            const int h_ = (n0 + ccol) / HDIM;
            const int m  = m0 + row;
            const int b_ = m >> 11;
            const int s_ = m & (SEQ - 1);
            const size_t base = ((size_t)(b_*NHEADS + h_) * SEQ + s_) * HDIM;
            #pragma unroll
            for (int c = 0; c < 64; c += 2) {
                float f0 = (src[c]   + bias_s[ccol+c])   * prescale;
                float f1 = (src[c+1] + bias_s[ccol+c+1]) * prescale;
                __nv_bfloat16 h0,h1,l0,l1; split2(f0,h0,l0); split2(f1,h1,l1);
                __nv_bfloat162 t;
                t.x=h0; t.y=h1; *reinterpret_cast<__nv_bfloat162*>(outH + base + c) = t;
                t.x=l0; t.y=l1; *reinterpret_cast<__nv_bfloat162*>(outL + base + c) = t;
            }
        } else {
            float* dst = outF + (size_t)(m0 + row) * D_MODEL + n0 + ccol;
            #pragma unroll
            for (int c = 0; c < 64; c += 4) {
                float4 o;
                o.x = src[c+0] + bias_s[ccol+c+0];
                o.y = src[c+1] + bias_s[ccol+c+1];
                o.z = src[c+2] + bias_s[ccol+c+2];
                o.w = src[c+3] + bias_s[ccol+c+3];
                *reinterpret_cast<float4*>(dst + c) = o;
            }
        }
    }
}

__global__ __launch_bounds__(256, 1) void qkv_proj_kernel(
    const float* __restrict__ bq, const float* __restrict__ bk, const float* __restrict__ bv)
{
    if (blockIdx.z == 0)
        gemm_bf16_body<0>(g_xqh, g_xql, g_wqh, g_wql, bq, g_qh, g_ql, nullptr, 8.0f);
    else if (blockIdx.z == 1)
        gemm_bf16_body<0>(g_xkh, g_xkl, g_wkh, g_wkl, bk, g_kh, g_kl, nullptr, 1.0f);
    else
        gemm_bf16_body<0>(g_xvh, g_xvl, g_wvh, g_wvl, bv, g_vh, g_vl, nullptr, 1.0f);
}

__global__ __launch_bounds__(256, 1) void out_proj_kernel(
    const float* __restrict__ bo, float* __restrict__ out)
{
    gemm_bf16_body<1>(g_ah, g_al, g_woh, g_wol, bo, nullptr, nullptr, out, 1.0f);
}

// =====================================================================
// FA2-style flash attention: raw mma.sync, register softmax, register O.
// 128 q-rows/block, 8 warps (16 rows each), 64-key tiles.
// Smem: Q staging + 2-deep K/V cp.async ring = 110592 B -> 2 CTAs/SM.
// =====================================================================
#define PBB 144                            // row pitch bytes (72 bf16)
#define OFF_QH 0
#define OFF_QL (128*PBB)                   // 18432
#define OFF_KV (2*128*PBB)                 // 36864
#define KV_MAT (64*PBB)                    // 9216
#define KV_STAGE (4*KV_MAT)                // 36864 (Kh,Kl,Vh,Vl)
#define ATTN_SMEM (OFF_KV + 2*KV_STAGE)    // 110592

__global__ __launch_bounds__(256, 2) void flash_attn_mma()
{
    extern __shared__ __align__(128) char smem[];
    const uint32_t sb = smem_u32(smem);

    const int tid  = threadIdx.x;
    const int wid  = tid >> 5;
    const int lane = tid & 31;
    const int q0   = blockIdx.x * 128;
    const int bh   = blockIdx.y;
    const int g    = lane >> 2;      // row group 0..7
    const int t    = lane & 3;       // col pair 0..3

    // ---- stage Q (hi/lo) into smem ----
    {
        const int r  = tid >> 1;
        const int ch = (tid & 1) * 32;
        const uint4* shp = reinterpret_cast<const uint4*>(g_qh + ((size_t)bh*SEQ + q0 + r)*HDIM + ch);
        const uint4* slp = reinterpret_cast<const uint4*>(g_ql + ((size_t)bh*SEQ + q0 + r)*HDIM + ch);
        uint4* dh = reinterpret_cast<uint4*>(smem + OFF_QH + r*PBB + ch*2);
        uint4* dl = reinterpret_cast<uint4*>(smem + OFF_QL + r*PBB + ch*2);
        #pragma unroll
        for (int i = 0; i < 4; i++) { dh[i] = shp[i]; dl[i] = slp[i]; }
    }

    // per-lane ldmatrix address components
    // Q (A operand, x4): lanes 0-15 rows, 16-31 rows at k+8
    const uint32_t qAddr = sb + OFF_QH + (uint32_t)((wid*16 + (lane & 15))*PBB + (lane >> 4)*16);
    // K (B operand, x4 non-trans): m0/m1 = n8 'a' (k lo/hi), m2/m3 = n8 'b'
    const uint32_t kOff = (uint32_t)(((lane & 7) + ((lane >> 4) << 3)) * PBB + ((lane >> 3) & 1) * 16);
    // V (B operand, x4 trans): m0/m1 = k lo/hi at hd 'a', m2/m3 at hd 'b'
    const uint32_t vOff = (uint32_t)((((lane & 7) + (((lane >> 3) & 1) << 3)) * PBB) + ((lane >> 4) & 1) * 16);

    auto issueKV = [&](int kt, int b) {
        const uint32_t base = sb + OFF_KV + (uint32_t)b * KV_STAGE;
        #pragma unroll
        for (int mat = 0; mat < 4; mat++) {
            const __nv_bfloat16* gsrc = (mat==0) ? g_kh : (mat==1) ? g_kl : (mat==2) ? g_vh : g_vl;
            #pragma unroll
            for (int half = 0; half < 2; half++) {
                const int chunk = half*256 + tid;
                const int row = chunk >> 3, col = chunk & 7;
                cp16(base + (uint32_t)mat*KV_MAT + row*PBB + col*16,
                     gsrc + (size_t)(bh*SEQ + kt*64 + row) * HDIM + col*8);
            }
        }
    };

    float o[8][4];
    #pragma unroll
    for (int ni = 0; ni < 8; ni++)
        #pragma unroll
        for (int c = 0; c < 4; c++) o[ni][c] = 0.f;
    float m0 = -1e30f, m1 = -1e30f, l0 = 0.f, l1 = 0.f;

    issueKV(0, 0); CP_COMMIT();

    for (int kt = 0; kt < SEQ/64; kt++) {
        if (kt < SEQ/64 - 1) { issueKV(kt+1, (kt+1)&1); CP_COMMIT(); CP_WAIT1(); }
        else                 { CP_WAIT0(); }
        __syncthreads();   // (a) stage kt visible (and Q on kt=0)

        const uint32_t Kb  = sb + OFF_KV + (uint32_t)(kt & 1) * KV_STAGE;
        const uint32_t Klb = Kb + KV_MAT;
        const uint32_t Vb  = Kb + 2*KV_MAT;
        const uint32_t Vlb = Kb + 3*KV_MAT;

        // ---- S = Q K^T (x8 via Q prescale), 3-pass, all-register ----
        float s[8][4];
        #pragma unroll
        for (int n8 = 0; n8 < 8; n8++)
            #pragma unroll
            for (int c = 0; c < 4; c++) s[n8][c] = 0.f;

        #pragma unroll
        for (int kk = 0; kk < 4; kk++) {
            uint32_t qh[4], ql[4];
            ldsm4(qh, qAddr + kk*32);
            ldsm4(ql, qAddr + (OFF_QL - OFF_QH) + kk*32);
            #pragma unroll
            for (int np = 0; np < 4; np++) {
                uint32_t bhf[4], blf[4];
                ldsm4(bhf, Kb  + np*16*PBB + kk*32 + kOff);
                ldsm4(blf, Klb + np*16*PBB + kk*32 + kOff);
                mma16816(s[2*np],   qh, bhf);     mma16816(s[2*np],   qh, blf);     mma16816(s[2*np],   ql, bhf);
                mma16816(s[2*np+1], qh, bhf+2);   mma16816(s[2*np+1], qh, blf+2);   mma16816(s[2*np+1], ql, bhf+2);
            }
        }

        // ---- register softmax (rows g, g+8; quad shfl over cols) ----
        float mx0 = -1e30f, mx1 = -1e30f;
        #pragma unroll
        for (int n8 = 0; n8 < 8; n8++) {
            mx0 = fmaxf(mx0, fmaxf(s[n8][0], s[n8][1]));
            mx1 = fmaxf(mx1, fmaxf(s[n8][2], s[n8][3]));
        }
        mx0 = fmaxf(mx0, __shfl_xor_sync(0xffffffffu, mx0, 1));
        mx0 = fmaxf(mx0, __shfl_xor_sync(0xffffffffu, mx0, 2));
        mx1 = fmaxf(mx1, __shfl_xor_sync(0xffffffffu, mx1, 1));
        mx1 = fmaxf(mx1, __shfl_xor_sync(0xffffffffu, mx1, 2));
        const float mn0 = fmaxf(m0, mx0), mn1 = fmaxf(m1, mx1);
        const float a0 = __expf(m0 - mn0), a1 = __expf(m1 - mn1);
        m0 = mn0; m1 = mn1;

        float sum0 = 0.f, sum1 = 0.f;
        #pragma unroll
        for (int n8 = 0; n8 < 8; n8++) {
            s[n8][0] = __expf(s[n8][0] - mn0);
            s[n8][1] = __expf(s[n8][1] - mn0);
            s[n8][2] = __expf(s[n8][2] - mn1);
            s[n8][3] = __expf(s[n8][3] - mn1);
            sum0 += s[n8][0] + s[n8][1];
            sum1 += s[n8][2] + s[n8][3];
        }
        sum0 += __shfl_xor_sync(0xffffffffu, sum0, 1);
        sum0 += __shfl_xor_sync(0xffffffffu, sum0, 2);
        sum1 += __shfl_xor_sync(0xffffffffu, sum1, 1);
        sum1 += __shfl_xor_sync(0xffffffffu, sum1, 2);
        l0 = l0*a0 + sum0;
        l1 = l1*a1 + sum1;

        // ---- rescale O, then O += P V (P from S registers; S-C == PV-A layout) ----
        #pragma unroll
        for (int ni = 0; ni < 8; ni++) {
            o[ni][0] *= a0; o[ni][1] *= a0;
            o[ni][2] *= a1; o[ni][3] *= a1;
        }

        #pragma unroll
        for (int kk = 0; kk < 4; kk++) {
            // P fragment for key-chunk kk = S tiles n8 = 2kk, 2kk+1
            uint32_t ph[4], pl[4];
            {
                __nv_bfloat16 h00,l00,h01,l01,h02,l02,h03,l03;
                __nv_bfloat16 h10,l10,h11,l11,h12,l12,h13,l13;
                split2(s[2*kk][0],   h00, l00); split2(s[2*kk][1],   h01, l01);
                split2(s[2*kk][2],   h02, l02); split2(s[2*kk][3],   h03, l03);
                split2(s[2*kk+1][0], h10, l10); split2(s[2*kk+1][1], h11, l11);
                split2(s[2*kk+1][2], h12, l12); split2(s[2*kk+1][3], h13, l13);
                ph[0] = packbf(h00, h01); pl[0] = packbf(l00, l01);   // row g,   k 0-7
                ph[1] = packbf(h02, h03); pl[1] = packbf(l02, l03);   // row g+8, k 0-7
                ph[2] = packbf(h10, h11); pl[2] = packbf(l10, l11);   // row g,   k 8-15
                ph[3] = packbf(h12, h13); pl[3] = packbf(l12, l13);   // row g+8, k 8-15
            }
            #pragma unroll
            for (int np = 0; np < 4; np++) {
                uint32_t vh[4], vl[4];
                ldsm4t(vh, Vb  + kk*16*PBB + np*32 + vOff);
                ldsm4t(vl, Vlb + kk*16*PBB + np*32 + vOff);
                mma16816(o[2*np],   ph, vh);     mma16816(o[2*np],   ph, vl);     mma16816(o[2*np],   pl, vh);
                mma16816(o[2*np+1], ph, vh+2);   mma16816(o[2*np+1], ph, vl+2);   mma16816(o[2*np+1], pl, vh+2);
            }
        }
        __syncthreads();   // (b) all warps done reading stage kt
    }

    // ---- epilogue: normalize, split, write bf16 hi/lo to [B,S,D] ----
    {
        const int b_ = bh / NHEADS;
        const int h_ = bh % NHEADS;
        const float i0 = 1.0f / l0, i1 = 1.0f / l1;
        const int r0 = q0 + wid*16 + g;
        const int r1 = r0 + 8;
        const size_t base0 = ((size_t)(b_*SEQ + r0)) * D_MODEL + h_*HDIM;
        const size_t base1 = ((size_t)(b_*SEQ + r1)) * D_MODEL + h_*HDIM;
        #pragma unroll
        for (int ni = 0; ni < 8; ni++) {
            const int col = ni*8 + t*2;
            __nv_bfloat16 h0,l0b,h1,l1b;
            split2(o[ni][0]*i0, h0, l0b); split2(o[ni][1]*i0, h1, l1b);
            *reinterpret_cast<uint32_t*>(g_ah + base0 + col) = packbf(h0, h1);
            *reinterpret_cast<uint32_t*>(g_al + base0 + col) = packbf(l0b, l1b);
            split2(o[ni][2]*i1, h0, l0b); split2(o[ni][3]*i1, h1, l1b);
            *reinterpret_cast<uint32_t*>(g_ah + base1 + col) = packbf(h0, h1);
            *reinterpret_cast<uint32_t*>(g_al + base1 + col) = packbf(l0b, l1b);
        }
    }
}

// =====================================================================
extern "C" void kernel_launch(void* const* d_in, const int* in_sizes, int n_in,
                              void* d_out, int out_size)
{
    const float* query = (const float*)d_in[0];
    const float* key   = (const float*)d_in[1];
    const float* value = (const float*)d_in[2];
    const float* bq    = (const float*)d_in[4];
    const float* bk    = (const float*)d_in[6];
    const float* bv    = (const float*)d_in[8];
    const float* Wq    = (const float*)d_in[3];
    const float* Wk    = (const float*)d_in[5];
    const float* Wv    = (const float*)d_in[7];
    const float* Wo    = (const float*)d_in[9];
    const float* bo    = (const float*)d_in[10];
    float* out = (float*)d_out;

    cudaFuncSetAttribute(qkv_proj_kernel, cudaFuncAttributeMaxDynamicSharedMemorySize, GEMM_SMEM);
    cudaFuncSetAttribute(out_proj_kernel, cudaFuncAttributeMaxDynamicSharedMemorySize, GEMM_SMEM);
    cudaFuncSetAttribute(flash_attn_mma, cudaFuncAttributeMaxDynamicSharedMemorySize, ATTN_SMEM);

    split_kernel<<<NELEM_X/4/256, 256>>>(query, 0, NELEM_X/4);
    split_kernel<<<NELEM_X/4/256, 256>>>(key,   1, NELEM_X/4);
    split_kernel<<<NELEM_X/4/256, 256>>>(value, 2, NELEM_X/4);
    split_kernel<<<NELEM_W/4/256, 256>>>(Wq, 3, NELEM_W/4);
    split_kernel<<<NELEM_W/4/256, 256>>>(Wk, 4, NELEM_W/4);
    split_kernel<<<NELEM_W/4/256, 256>>>(Wv, 5, NELEM_W/4);
    split_kernel<<<NELEM_W/4/256, 256>>>(Wo, 6, NELEM_W/4);

    dim3 qkv_grid(D_MODEL/128, MTOT/128, 3);   // (8, 32, 3)
    qkv_proj_kernel<<<qkv_grid, 256, GEMM_SMEM>>>(bq, bk, bv);

    dim3 attn_grid(SEQ/128, BATCH*NHEADS);     // (16, 32)
    flash_attn_mma<<<attn_grid, 256, ATTN_SMEM>>>();

    dim3 oproj_grid(D_MODEL/128, MTOT/128);    // (8, 32)
    out_proj_kernel<<<oproj_grid, 256, GEMM_SMEM>>>(bo, out);
}

// round 12
// speedup vs baseline: 3.8152x; 1.3184x over previous
#include <cuda_runtime.h>
#include <cuda_bf16.h>
#include <math.h>
#include <stdint.h>

#define D_MODEL 1024
#define NHEADS  16
#define HDIM    64
#define BATCH   2
#define SEQ     2048
#define MTOT    (BATCH*SEQ)
#define NELEM_X (MTOT*D_MODEL)      // 4194304
#define NELEM_W (D_MODEL*D_MODEL)   // 1048576

// ---------------- scratch (device globals: no allocation allowed) ----------------
__device__ __nv_bfloat16 g_xqh[NELEM_X], g_xql[NELEM_X];
__device__ __nv_bfloat16 g_xkh[NELEM_X], g_xkl[NELEM_X];
__device__ __nv_bfloat16 g_xvh[NELEM_X], g_xvl[NELEM_X];
__device__ __nv_bfloat16 g_wqh[NELEM_W], g_wql[NELEM_W];
__device__ __nv_bfloat16 g_wkh[NELEM_W], g_wkl[NELEM_W];
__device__ __nv_bfloat16 g_wvh[NELEM_W], g_wvl[NELEM_W];
__device__ __nv_bfloat16 g_woh[NELEM_W], g_wol[NELEM_W];
__device__ __nv_bfloat16 g_qh[NELEM_X],  g_ql[NELEM_X];   // [B,H,S,Hd], pre-scaled x8
__device__ __nv_bfloat16 g_kh[NELEM_X],  g_kl[NELEM_X];   // [B,H,S,Hd]
__device__ __nv_bfloat16 g_vh[NELEM_X],  g_vl[NELEM_X];   // [B,H,S,Hd]
__device__ __nv_bfloat16 g_ah[NELEM_X],  g_al[NELEM_X];   // [B,S,D]

// 2-term bf16 split: x ~= hi + lo, |err| ~ 2^-17 |x|
__device__ __forceinline__ void split2(float x, __nv_bfloat16& h, __nv_bfloat16& l) {
    h = __float2bfloat16(x);
    l = __float2bfloat16(x - __bfloat162float(h));
}

__device__ __forceinline__ uint32_t smem_u32(const void* p) {
    uint32_t a;
    asm("{ .reg .u64 t; cvta.to.shared.u64 t, %1; cvt.u32.u64 %0, t; }" : "=r"(a) : "l"(p));
    return a;
}
__device__ __forceinline__ void cp16(uint32_t dst, const void* src) {
    asm volatile("cp.async.cg.shared.global [%0], [%1], 16;" :: "r"(dst), "l"(src));
}
#define CP_COMMIT() asm volatile("cp.async.commit_group;" ::: "memory")
#define CP_WAIT0()  asm volatile("cp.async.wait_group 0;" ::: "memory")
#define CP_WAIT1()  asm volatile("cp.async.wait_group 1;" ::: "memory")

// ---- raw mma.sync helpers (defined layouts, portable PTX) ----
__device__ __forceinline__ void ldsm4(uint32_t* d, uint32_t a) {
    asm volatile("ldmatrix.sync.aligned.m8n8.x4.shared.b16 {%0,%1,%2,%3}, [%4];"
        : "=r"(d[0]), "=r"(d[1]), "=r"(d[2]), "=r"(d[3]) : "r"(a));
}
__device__ __forceinline__ void ldsm4t(uint32_t* d, uint32_t a) {
    asm volatile("ldmatrix.sync.aligned.m8n8.x4.trans.shared.b16 {%0,%1,%2,%3}, [%4];"
        : "=r"(d[0]), "=r"(d[1]), "=r"(d[2]), "=r"(d[3]) : "r"(a));
}
__device__ __forceinline__ void mma16816(float* c, const uint32_t* a, const uint32_t* b) {
    asm volatile("mma.sync.aligned.m16n8k16.row.col.f32.bf16.bf16.f32 "
        "{%0,%1,%2,%3}, {%4,%5,%6,%7}, {%8,%9}, {%0,%1,%2,%3};"
        : "+f"(c[0]), "+f"(c[1]), "+f"(c[2]), "+f"(c[3])
        : "r"(a[0]), "r"(a[1]), "r"(a[2]), "r"(a[3]), "r"(b[0]), "r"(b[1]));
}
__device__ __forceinline__ uint32_t packbf(__nv_bfloat16 lo, __nv_bfloat16 hi) {
    __nv_bfloat162 t; t.x = lo; t.y = hi;
    return *reinterpret_cast<uint32_t*>(&t);
}

// =====================================================================
// fused split kernel: 7 arrays in one launch (block-range dispatch)
// =====================================================================
#define XBLK (NELEM_X/4/256)   // 4096
#define WBLK (NELEM_W/4/256)   // 1024
#define SPLIT_BLOCKS (3*XBLK + 4*WBLK)

__global__ __launch_bounds__(256) void split_all_kernel(
    const float* __restrict__ q, const float* __restrict__ k, const float* __restrict__ v,
    const float* __restrict__ wq, const float* __restrict__ wk,
    const float* __restrict__ wv, const float* __restrict__ wo)
{
    const int bid = blockIdx.x;
    const float* src; __nv_bfloat16 *h, *l; int i;
    if (bid < 3*XBLK) {
        const int which = bid / XBLK;
        i = (bid - which*XBLK) * 256 + threadIdx.x;
        src = (which == 0) ? q : (which == 1) ? k : v;
        h   = (which == 0) ? g_xqh : (which == 1) ? g_xkh : g_xvh;
        l   = (which == 0) ? g_xql : (which == 1) ? g_xkl : g_xvl;
    } else {
        const int wb = bid - 3*XBLK;
        const int which = wb / WBLK;
        i = (wb - which*WBLK) * 256 + threadIdx.x;
        src = (which == 0) ? wq : (which == 1) ? wk : (which == 2) ? wv : wo;
        h   = (which == 0) ? g_wqh : (which == 1) ? g_wkh : (which == 2) ? g_wvh : g_woh;
        l   = (which == 0) ? g_wql : (which == 1) ? g_wkl : (which == 2) ? g_wvl : g_wol;
    }
    float4 val = reinterpret_cast<const float4*>(src)[i];
    __nv_bfloat16 h0,h1,h2,h3,l0,l1,l2,l3;
    split2(val.x,h0,l0); split2(val.y,h1,l1); split2(val.z,h2,l2); split2(val.w,h3,l3);
    __nv_bfloat162 t;
    __nv_bfloat162* H = reinterpret_cast<__nv_bfloat162*>(h) + (size_t)i*2;
    __nv_bfloat162* L = reinterpret_cast<__nv_bfloat162*>(l) + (size_t)i*2;
    t.x=h0; t.y=h1; H[0]=t;  t.x=h2; t.y=h3; H[1]=t;
    t.x=l0; t.y=l1; L[0]=t;  t.x=l2; t.y=l3; L[1]=t;
}

// =====================================================================
// bf16 GEMM via raw mma.sync: C = (Xh+Xl)(Wh+Wl)^T + bias (3-pass)
// BM=BN=128, BK=32, 8 warps (4m x 2n), warp tile 32x64.
// Register epilogue (no smem round-trip). 80KB smem -> 2 CTAs/SM.
// =====================================================================
#define SPB 80                     // stage row pitch bytes (32 bf16 data + pad)
#define MAT_BYTES (128*SPB)        // 10240
#define STAGE_BYTES (4*MAT_BYTES)  // 40960 (Ah,Al,Bh,Bl)
#define GEMM_SMEM (2*STAGE_BYTES)  // 81920

// OUT_MODE: 0 = split-heads bf16 hi/lo pair,  1 = f32 row-major
template<int OUT_MODE>
__device__ __forceinline__ void gemm_mma_body(
    const __nv_bfloat16* __restrict__ Xh, const __nv_bfloat16* __restrict__ Xl,
    const __nv_bfloat16* __restrict__ Wh, const __nv_bfloat16* __restrict__ Wl,
    const float* __restrict__ bias,
    __nv_bfloat16* outH, __nv_bfloat16* outL, float* outF, float prescale)
{
    extern __shared__ __align__(128) char smem[];
    const uint32_t sb = smem_u32(smem);

    const int tid  = threadIdx.x;
    const int wid  = tid >> 5;
    const int lane = tid & 31;
    const int m0   = blockIdx.y * 128;
    const int n0   = blockIdx.x * 128;
    const int mw   = wid >> 1;       // 0..3
    const int nw   = wid & 1;        // 0..1
    const int g    = lane >> 2;      // row group 0..7
    const int t    = lane & 3;       // col pair 0..3

    float acc[2][8][4];
    #pragma unroll
    for (int mi = 0; mi < 2; mi++)
        #pragma unroll
        for (int n8 = 0; n8 < 8; n8++)
            #pragma unroll
            for (int c = 0; c < 4; c++) acc[mi][n8][c] = 0.f;

    // ldmatrix lane-address components
    const uint32_t aOff = (uint32_t)((lane & 15)*SPB + (lane >> 4)*16);
    const uint32_t bOff = (uint32_t)(((lane & 7) + ((lane >> 4) << 3))*SPB + ((lane >> 3) & 1)*16);

    auto issue = [&](int s, int b) {
        const uint32_t base = sb + (uint32_t)b * STAGE_BYTES;
        #pragma unroll
        for (int mat = 0; mat < 4; mat++) {
            const __nv_bfloat16* gsrc = (mat==0) ? Xh : (mat==1) ? Xl : (mat==2) ? Wh : Wl;
            const int rbase = (mat < 2) ? m0 : n0;
            #pragma unroll
            for (int half = 0; half < 2; half++) {
                const int chunk = half*256 + tid;       // 0..511
                const int row = chunk >> 2, col = chunk & 3;
                cp16(base + (uint32_t)mat*MAT_BYTES + row*SPB + col*16,
                     gsrc + (size_t)(rbase + row) * D_MODEL + s*32 + col*8);
            }
        }
    };

    issue(0, 0); CP_COMMIT();

    for (int s = 0; s < D_MODEL/32; s++) {
        if (s < D_MODEL/32 - 1) { issue(s+1, (s+1)&1); CP_COMMIT(); CP_WAIT1(); }
        else                    { CP_WAIT0(); }
        __syncthreads();   // stage s visible

        const uint32_t Ahb = sb + (uint32_t)(s & 1) * STAGE_BYTES;
        const uint32_t Alb = Ahb + MAT_BYTES;
        const uint32_t Bhb = Ahb + 2*MAT_BYTES;
        const uint32_t Blb = Ahb + 3*MAT_BYTES;

        #pragma unroll
        for (int kk = 0; kk < 2; kk++) {
            uint32_t ah[2][4], al[2][4];
            #pragma unroll
            for (int mi = 0; mi < 2; mi++) {
                ldsm4(ah[mi], Ahb + (uint32_t)((mw*32 + mi*16)*SPB) + kk*32 + aOff);
                ldsm4(al[mi], Alb + (uint32_t)((mw*32 + mi*16)*SPB) + kk*32 + aOff);
            }
            #pragma unroll
            for (int np = 0; np < 4; np++) {
                uint32_t bh4[4], bl4[4];
                ldsm4(bh4, Bhb + (uint32_t)((nw*64 + np*16)*SPB) + kk*32 + bOff);
                ldsm4(bl4, Blb + (uint32_t)((nw*64 + np*16)*SPB) + kk*32 + bOff);
                #pragma unroll
                for (int mi = 0; mi < 2; mi++) {
                    mma16816(acc[mi][2*np],   ah[mi], bh4);
                    mma16816(acc[mi][2*np],   ah[mi], bl4);
                    mma16816(acc[mi][2*np],   al[mi], bh4);
                    mma16816(acc[mi][2*np+1], ah[mi], bh4+2);
                    mma16816(acc[mi][2*np+1], ah[mi], bl4+2);
                    mma16816(acc[mi][2*np+1], al[mi], bh4+2);
                }
            }
        }
        __syncthreads();   // all warps done reading before re-issue
    }

    // ---- register epilogue: thread holds rows (g, g+8), cols (2t, 2t+1) per n8 ----
    #pragma unroll
    for (int mi = 0; mi < 2; mi++) {
        const int r0 = m0 + mw*32 + mi*16 + g;
        const int r1 = r0 + 8;
        #pragma unroll
        for (int n8 = 0; n8 < 8; n8++) {
            const int ncol = n0 + nw*64 + n8*8 + t*2;
            const float2 bv2 = *reinterpret_cast<const float2*>(bias + ncol);
            float c00 = acc[mi][n8][0] + bv2.x, c01 = acc[mi][n8][1] + bv2.y;
            float c10 = acc[mi][n8][2] + bv2.x, c11 = acc[mi][n8][3] + bv2.y;
            if (OUT_MODE == 0) {
                c00 *= prescale; c01 *= prescale; c10 *= prescale; c11 *= prescale;
                const int h_ = ncol >> 6, d0 = ncol & 63;
                const size_t base0 = (((size_t)((r0 >> 11)*NHEADS + h_) * SEQ + (r0 & (SEQ-1))) * HDIM) + d0;
                const size_t base1 = (((size_t)((r1 >> 11)*NHEADS + h_) * SEQ + (r1 & (SEQ-1))) * HDIM) + d0;
                __nv_bfloat16 h0,l0,h1,l1;
                split2(c00,h0,l0); split2(c01,h1,l1);
                *reinterpret_cast<uint32_t*>(outH + base0) = packbf(h0,h1);
                *reinterpret_cast<uint32_t*>(outL + base0) = packbf(l0,l1);
                split2(c10,h0,l0); split2(c11,h1,l1);
                *reinterpret_cast<uint32_t*>(outH + base1) = packbf(h0,h1);
                *reinterpret_cast<uint32_t*>(outL + base1) = packbf(l0,l1);
            } else {
                float2* d0p = reinterpret_cast<float2*>(outF + (size_t)r0 * D_MODEL + ncol);
                float2* d1p = reinterpret_cast<float2*>(outF + (size_t)r1 * D_MODEL + ncol);
                *d0p = make_float2(c00, c01);
                *d1p = make_float2(c10, c11);
            }
        }
    }
}

__global__ __launch_bounds__(256, 2) void qkv_proj_kernel(
    const float* __restrict__ bq, const float* __restrict__ bk, const float* __restrict__ bv)
{
    if (blockIdx.z == 0)
        gemm_mma_body<0>(g_xqh, g_xql, g_wqh, g_wql, bq, g_qh, g_ql, nullptr, 8.0f);
    else if (blockIdx.z == 1)
        gemm_mma_body<0>(g_xkh, g_xkl, g_wkh, g_wkl, bk, g_kh, g_kl, nullptr, 1.0f);
    else
        gemm_mma_body<0>(g_xvh, g_xvl, g_wvh, g_wvl, bv, g_vh, g_vl, nullptr, 1.0f);
}

__global__ __launch_bounds__(256, 2) void out_proj_kernel(
    const float* __restrict__ bo, float* __restrict__ out)
{
    gemm_mma_body<1>(g_ah, g_al, g_woh, g_wol, bo, nullptr, nullptr, out, 1.0f);
}

// =====================================================================
// FA2-style flash attention: raw mma.sync, register softmax, register O.
// 128 q-rows/block, 8 warps, 64-key tiles. 2-deep cp.async K/V ring.
// =====================================================================
#define PBB 144                            // row pitch bytes (72 bf16)
#define OFF_QH 0
#define OFF_QL (128*PBB)                   // 18432
#define OFF_KV (2*128*PBB)                 // 36864
#define KV_MAT (64*PBB)                    // 9216
#define KV_STAGE (4*KV_MAT)                // 36864 (Kh,Kl,Vh,Vl)
#define ATTN_SMEM (OFF_KV + 2*KV_STAGE)    // 110592

__global__ __launch_bounds__(256, 2) void flash_attn_mma()
{
    extern __shared__ __align__(128) char smem[];
    const uint32_t sb = smem_u32(smem);

    const int tid  = threadIdx.x;
    const int wid  = tid >> 5;
    const int lane = tid & 31;
    const int q0   = blockIdx.x * 128;
    const int bh   = blockIdx.y;
    const int g    = lane >> 2;
    const int t    = lane & 3;

    {
        const int r  = tid >> 1;
        const int ch = (tid & 1) * 32;
        const uint4* shp = reinterpret_cast<const uint4*>(g_qh + ((size_t)bh*SEQ + q0 + r)*HDIM + ch);
        const uint4* slp = reinterpret_cast<const uint4*>(g_ql + ((size_t)bh*SEQ + q0 + r)*HDIM + ch);
        uint4* dh = reinterpret_cast<uint4*>(smem + OFF_QH + r*PBB + ch*2);
        uint4* dl = reinterpret_cast<uint4*>(smem + OFF_QL + r*PBB + ch*2);
        #pragma unroll
        for (int i = 0; i < 4; i++) { dh[i] = shp[i]; dl[i] = slp[i]; }
    }

    const uint32_t qAddr = sb + OFF_QH + (uint32_t)((wid*16 + (lane & 15))*PBB + (lane >> 4)*16);
    const uint32_t kOff = (uint32_t)(((lane & 7) + ((lane >> 4) << 3)) * PBB + ((lane >> 3) & 1) * 16);
    const uint32_t vOff = (uint32_t)((((lane & 7) + (((lane >> 3) & 1) << 3)) * PBB) + ((lane >> 4) & 1) * 16);

    auto issueKV = [&](int kt, int b) {
        const uint32_t base = sb + OFF_KV + (uint32_t)b * KV_STAGE;
        #pragma unroll
        for (int mat = 0; mat < 4; mat++) {
            const __nv_bfloat16* gsrc = (mat==0) ? g_kh : (mat==1) ? g_kl : (mat==2) ? g_vh : g_vl;
            #pragma unroll
            for (int half = 0; half < 2; half++) {
                const int chunk = half*256 + tid;
                const int row = chunk >> 3, col = chunk & 7;
                cp16(base + (uint32_t)mat*KV_MAT + row*PBB + col*16,
                     gsrc + (size_t)(bh*SEQ + kt*64 + row) * HDIM + col*8);
            }
        }
    };

    float o[8][4];
    #pragma unroll
    for (int ni = 0; ni < 8; ni++)
        #pragma unroll
        for (int c = 0; c < 4; c++) o[ni][c] = 0.f;
    float m0 = -1e30f, m1 = -1e30f, l0 = 0.f, l1 = 0.f;

    issueKV(0, 0); CP_COMMIT();

    for (int kt = 0; kt < SEQ/64; kt++) {
        if (kt < SEQ/64 - 1) { issueKV(kt+1, (kt+1)&1); CP_COMMIT(); CP_WAIT1(); }
        else                 { CP_WAIT0(); }
        __syncthreads();

        const uint32_t Kb  = sb + OFF_KV + (uint32_t)(kt & 1) * KV_STAGE;
        const uint32_t Klb = Kb + KV_MAT;
        const uint32_t Vb  = Kb + 2*KV_MAT;
        const uint32_t Vlb = Kb + 3*KV_MAT;

        float s[8][4];
        #pragma unroll
        for (int n8 = 0; n8 < 8; n8++)
            #pragma unroll
            for (int c = 0; c < 4; c++) s[n8][c] = 0.f;

        #pragma unroll
        for (int kk = 0; kk < 4; kk++) {
            uint32_t qh[4], ql[4];
            ldsm4(qh, qAddr + kk*32);
            ldsm4(ql, qAddr + (OFF_QL - OFF_QH) + kk*32);
            #pragma unroll
            for (int np = 0; np < 4; np++) {
                uint32_t bhf[4], blf[4];
                ldsm4(bhf, Kb  + np*16*PBB + kk*32 + kOff);
                ldsm4(blf, Klb + np*16*PBB + kk*32 + kOff);
                mma16816(s[2*np],   qh, bhf);     mma16816(s[2*np],   qh, blf);     mma16816(s[2*np],   ql, bhf);
                mma16816(s[2*np+1], qh, bhf+2);   mma16816(s[2*np+1], qh, blf+2);   mma16816(s[2*np+1], ql, bhf+2);
            }
        }

        float mx0 = -1e30f, mx1 = -1e30f;
        #pragma unroll
        for (int n8 = 0; n8 < 8; n8++) {
            mx0 = fmaxf(mx0, fmaxf(s[n8][0], s[n8][1]));
            mx1 = fmaxf(mx1, fmaxf(s[n8][2], s[n8][3]));
        }
        mx0 = fmaxf(mx0, __shfl_xor_sync(0xffffffffu, mx0, 1));
        mx0 = fmaxf(mx0, __shfl_xor_sync(0xffffffffu, mx0, 2));
        mx1 = fmaxf(mx1, __shfl_xor_sync(0xffffffffu, mx1, 1));
        mx1 = fmaxf(mx1, __shfl_xor_sync(0xffffffffu, mx1, 2));
        const float mn0 = fmaxf(m0, mx0), mn1 = fmaxf(m1, mx1);
        const float a0 = __expf(m0 - mn0), a1 = __expf(m1 - mn1);
        m0 = mn0; m1 = mn1;

        float sum0 = 0.f, sum1 = 0.f;
        #pragma unroll
        for (int n8 = 0; n8 < 8; n8++) {
            s[n8][0] = __expf(s[n8][0] - mn0);
            s[n8][1] = __expf(s[n8][1] - mn0);
            s[n8][2] = __expf(s[n8][2] - mn1);
            s[n8][3] = __expf(s[n8][3] - mn1);
            sum0 += s[n8][0] + s[n8][1];
            sum1 += s[n8][2] + s[n8][3];
        }
        sum0 += __shfl_xor_sync(0xffffffffu, sum0, 1);
        sum0 += __shfl_xor_sync(0xffffffffu, sum0, 2);
        sum1 += __shfl_xor_sync(0xffffffffu, sum1, 1);
        sum1 += __shfl_xor_sync(0xffffffffu, sum1, 2);
        l0 = l0*a0 + sum0;
        l1 = l1*a1 + sum1;

        #pragma unroll
        for (int ni = 0; ni < 8; ni++) {
            o[ni][0] *= a0; o[ni][1] *= a0;
            o[ni][2] *= a1; o[ni][3] *= a1;
        }

        #pragma unroll
        for (int kk = 0; kk < 4; kk++) {
            uint32_t ph[4], pl[4];
            {
                __nv_bfloat16 h00,l00,h01,l01,h02,l02,h03,l03;
                __nv_bfloat16 h10,l10,h11,l11,h12,l12,h13,l13;
                split2(s[2*kk][0],   h00, l00); split2(s[2*kk][1],   h01, l01);
                split2(s[2*kk][2],   h02, l02); split2(s[2*kk][3],   h03, l03);
                split2(s[2*kk+1][0], h10, l10); split2(s[2*kk+1][1], h11, l11);
                split2(s[2*kk+1][2], h12, l12); split2(s[2*kk+1][3], h13, l13);
                ph[0] = packbf(h00, h01); pl[0] = packbf(l00, l01);
                ph[1] = packbf(h02, h03); pl[1] = packbf(l02, l03);
                ph[2] = packbf(h10, h11); pl[2] = packbf(l10, l11);
                ph[3] = packbf(h12, h13); pl[3] = packbf(l12, l13);
            }
            #pragma unroll
            for (int np = 0; np < 4; np++) {
                uint32_t vh[4], vl[4];
                ldsm4t(vh, Vb  + kk*16*PBB + np*32 + vOff);
                ldsm4t(vl, Vlb + kk*16*PBB + np*32 + vOff);
                mma16816(o[2*np],   ph, vh);     mma16816(o[2*np],   ph, vl);     mma16816(o[2*np],   pl, vh);
                mma16816(o[2*np+1], ph, vh+2);   mma16816(o[2*np+1], ph, vl+2);   mma16816(o[2*np+1], pl, vh+2);
            }
        }
        __syncthreads();
    }

    {
        const int b_ = bh / NHEADS;
        const int h_ = bh % NHEADS;
        const float i0 = 1.0f / l0, i1 = 1.0f / l1;
        const int r0 = q0 + wid*16 + g;
        const int r1 = r0 + 8;
        const size_t base0 = ((size_t)(b_*SEQ + r0)) * D_MODEL + h_*HDIM;
        const size_t base1 = ((size_t)(b_*SEQ + r1)) * D_MODEL + h_*HDIM;
        #pragma unroll
        for (int ni = 0; ni < 8; ni++) {
            const int col = ni*8 + t*2;
            __nv_bfloat16 h0,l0b,h1,l1b;
            split2(o[ni][0]*i0, h0, l0b); split2(o[ni][1]*i0, h1, l1b);
            *reinterpret_cast<uint32_t*>(g_ah + base0 + col) = packbf(h0, h1);
            *reinterpret_cast<uint32_t*>(g_al + base0 + col) = packbf(l0b, l1b);
            split2(o[ni][2]*i1, h0, l0b); split2(o[ni][3]*i1, h1, l1b);
            *reinterpret_cast<uint32_t*>(g_ah + base1 + col) = packbf(h0, h1);
            *reinterpret_cast<uint32_t*>(g_al + base1 + col) = packbf(l0b, l1b);
        }
    }
}

// =====================================================================
extern "C" void kernel_launch(void* const* d_in, const int* in_sizes, int n_in,
                              void* d_out, int out_size)
{
    const float* query = (const float*)d_in[0];
    const float* key   = (const float*)d_in[1];
    const float* value = (const float*)d_in[2];
    const float* Wq    = (const float*)d_in[3];
    const float* bq    = (const float*)d_in[4];
    const float* Wk    = (const float*)d_in[5];
    const float* bk    = (const float*)d_in[6];
    const float* Wv    = (const float*)d_in[7];
    const float* bv    = (const float*)d_in[8];
    const float* Wo    = (const float*)d_in[9];
    const float* bo    = (const float*)d_in[10];
    float* out = (float*)d_out;

    cudaFuncSetAttribute(qkv_proj_kernel, cudaFuncAttributeMaxDynamicSharedMemorySize, GEMM_SMEM);
    cudaFuncSetAttribute(out_proj_kernel, cudaFuncAttributeMaxDynamicSharedMemorySize, GEMM_SMEM);
    cudaFuncSetAttribute(flash_attn_mma, cudaFuncAttributeMaxDynamicSharedMemorySize, ATTN_SMEM);

    split_all_kernel<<<SPLIT_BLOCKS, 256>>>(query, key, value, Wq, Wk, Wv, Wo);

    dim3 qkv_grid(D_MODEL/128, MTOT/128, 3);   // (8, 32, 3)
    qkv_proj_kernel<<<qkv_grid, 256, GEMM_SMEM>>>(bq, bk, bv);

    dim3 attn_grid(SEQ/128, BATCH*NHEADS);     // (16, 32)
    flash_attn_mma<<<attn_grid, 256, ATTN_SMEM>>>();

    dim3 oproj_grid(D_MODEL/128, MTOT/128);    // (8, 32)
    out_proj_kernel<<<oproj_grid, 256, GEMM_SMEM>>>(bo, out);
}

// round 15
// speedup vs baseline: 3.8518x; 1.0096x over previous
#include <cuda_runtime.h>
#include <cuda_bf16.h>
#include <math.h>
#include <stdint.h>

#define D_MODEL 1024
#define NHEADS  16
#define HDIM    64
#define BATCH   2
#define SEQ     2048
#define MTOT    (BATCH*SEQ)
#define NELEM_X (MTOT*D_MODEL)      // 4194304
#define NELEM_W (D_MODEL*D_MODEL)   // 1048576

// ---------------- scratch (device globals: no allocation allowed) ----------------
__device__ __nv_bfloat16 g_xqh[NELEM_X], g_xql[NELEM_X];
__device__ __nv_bfloat16 g_xkh[NELEM_X], g_xkl[NELEM_X];
__device__ __nv_bfloat16 g_xvh[NELEM_X], g_xvl[NELEM_X];
__device__ __nv_bfloat16 g_wqh[NELEM_W], g_wql[NELEM_W];
__device__ __nv_bfloat16 g_wkh[NELEM_W], g_wkl[NELEM_W];
__device__ __nv_bfloat16 g_wvh[NELEM_W], g_wvl[NELEM_W];
__device__ __nv_bfloat16 g_woh[NELEM_W], g_wol[NELEM_W];
__device__ __nv_bfloat16 g_qh[NELEM_X],  g_ql[NELEM_X];   // [B,H,S,Hd], pre-scaled x8
__device__ __nv_bfloat16 g_kh[NELEM_X],  g_kl[NELEM_X];   // [B,H,S,Hd]
__device__ __nv_bfloat16 g_vh[NELEM_X],  g_vl[NELEM_X];   // [B,H,S,Hd]
__device__ __nv_bfloat16 g_ah[NELEM_X],  g_al[NELEM_X];   // [B,S,D]

// 2-term bf16 split: x ~= hi + lo, |err| ~ 2^-17 |x|
__device__ __forceinline__ void split2(float x, __nv_bfloat16& h, __nv_bfloat16& l) {
    h = __float2bfloat16(x);
    l = __float2bfloat16(x - __bfloat162float(h));
}

__device__ __forceinline__ uint32_t smem_u32(const void* p) {
    uint32_t a;
    asm("{ .reg .u64 t; cvta.to.shared.u64 t, %1; cvt.u32.u64 %0, t; }" : "=r"(a) : "l"(p));
    return a;
}
__device__ __forceinline__ void cp16(uint32_t dst, const void* src) {
    asm volatile("cp.async.cg.shared.global [%0], [%1], 16;" :: "r"(dst), "l"(src));
}
#define CP_COMMIT() asm volatile("cp.async.commit_group;" ::: "memory")
#define CP_WAIT0()  asm volatile("cp.async.wait_group 0;" ::: "memory")

// ---- raw mma.sync helpers (defined layouts, portable PTX) ----
__device__ __forceinline__ void ldsm4(uint32_t* d, uint32_t a) {
    asm volatile("ldmatrix.sync.aligned.m8n8.x4.shared.b16 {%0,%1,%2,%3}, [%4];"
        : "=r"(d[0]), "=r"(d[1]), "=r"(d[2]), "=r"(d[3]) : "r"(a));
}
__device__ __forceinline__ void ldsm4t(uint32_t* d, uint32_t a) {
    asm volatile("ldmatrix.sync.aligned.m8n8.x4.trans.shared.b16 {%0,%1,%2,%3}, [%4];"
        : "=r"(d[0]), "=r"(d[1]), "=r"(d[2]), "=r"(d[3]) : "r"(a));
}
__device__ __forceinline__ void mma16816(float* c, const uint32_t* a, const uint32_t* b) {
    asm volatile("mma.sync.aligned.m16n8k16.row.col.f32.bf16.bf16.f32 "
        "{%0,%1,%2,%3}, {%4,%5,%6,%7}, {%8,%9}, {%0,%1,%2,%3};"
        : "+f"(c[0]), "+f"(c[1]), "+f"(c[2]), "+f"(c[3])
        : "r"(a[0]), "r"(a[1]), "r"(a[2]), "r"(a[3]), "r"(b[0]), "r"(b[1]));
}
__device__ __forceinline__ uint32_t packbf(__nv_bfloat16 lo, __nv_bfloat16 hi) {
    __nv_bfloat162 t; t.x = lo; t.y = hi;
    return *reinterpret_cast<uint32_t*>(&t);
}

// =====================================================================
// fused split kernel: 7 arrays in one launch (block-range dispatch)
// =====================================================================
#define XBLK (NELEM_X/4/256)   // 4096
#define WBLK (NELEM_W/4/256)   // 1024
#define SPLIT_BLOCKS (3*XBLK + 4*WBLK)

__global__ __launch_bounds__(256) void split_all_kernel(
    const float* __restrict__ q, const float* __restrict__ k, const float* __restrict__ v,
    const float* __restrict__ wq, const float* __restrict__ wk,
    const float* __restrict__ wv, const float* __restrict__ wo)
{
    const int bid = blockIdx.x;
    const float* src; __nv_bfloat16 *h, *l; int i;
    if (bid < 3*XBLK) {
        const int which = bid / XBLK;
        i = (bid - which*XBLK) * 256 + threadIdx.x;
        src = (which == 0) ? q : (which == 1) ? k : v;
        h   = (which == 0) ? g_xqh : (which == 1) ? g_xkh : g_xvh;
        l   = (which == 0) ? g_xql : (which == 1) ? g_xkl : g_xvl;
    } else {
        const int wb = bid - 3*XBLK;
        const int which = wb / WBLK;
        i = (wb - which*WBLK) * 256 + threadIdx.x;
        src = (which == 0) ? wq : (which == 1) ? wk : (which == 2) ? wv : wo;
        h   = (which == 0) ? g_wqh : (which == 1) ? g_wkh : (which == 2) ? g_wvh : g_woh;
        l   = (which == 0) ? g_wql : (which == 1) ? g_wkl : (which == 2) ? g_wvl : g_wol;
    }
    float4 val = reinterpret_cast<const float4*>(src)[i];
    __nv_bfloat16 h0,h1,h2,h3,l0,l1,l2,l3;
    split2(val.x,h0,l0); split2(val.y,h1,l1); split2(val.z,h2,l2); split2(val.w,h3,l3);
    __nv_bfloat162 t;
    __nv_bfloat162* H = reinterpret_cast<__nv_bfloat162*>(h) + (size_t)i*2;
    __nv_bfloat162* L = reinterpret_cast<__nv_bfloat162*>(l) + (size_t)i*2;
    t.x=h0; t.y=h1; H[0]=t;  t.x=h2; t.y=h3; H[1]=t;
    t.x=l0; t.y=l1; L[0]=t;  t.x=l2; t.y=l3; L[1]=t;
}

// =====================================================================
// bf16 GEMM via raw mma.sync: C = (Xh+Xl)(Wh+Wl)^T + bias (3-pass)
// BM=BN=128, BK=32, 8 warps (4m x 2n), warp tile 32x64.
// SINGLE barrier per stage: wait -> barrier -> issue(s+1) -> MMAs.
// =====================================================================
#define SPB 80                     // stage row pitch bytes (32 bf16 data + pad)
#define MAT_BYTES (128*SPB)        // 10240
#define STAGE_BYTES (4*MAT_BYTES)  // 40960 (Ah,Al,Bh,Bl)
#define GEMM_SMEM (2*STAGE_BYTES)  // 81920

// OUT_MODE: 0 = split-heads bf16 hi/lo pair,  1 = f32 row-major
template<int OUT_MODE>
__device__ __forceinline__ void gemm_mma_body(
    const __nv_bfloat16* __restrict__ Xh, const __nv_bfloat16* __restrict__ Xl,
    const __nv_bfloat16* __restrict__ Wh, const __nv_bfloat16* __restrict__ Wl,
    const float* __restrict__ bias,
    __nv_bfloat16* outH, __nv_bfloat16* outL, float* outF, float prescale)
{
    extern __shared__ __align__(128) char smem[];
    const uint32_t sb = smem_u32(smem);

    const int tid  = threadIdx.x;
    const int wid  = tid >> 5;
    const int lane = tid & 31;
    const int m0   = blockIdx.y * 128;
    const int n0   = blockIdx.x * 128;
    const int mw   = wid >> 1;       // 0..3
    const int nw   = wid & 1;        // 0..1
    const int g    = lane >> 2;      // row group 0..7
    const int t    = lane & 3;       // col pair 0..3

    float acc[2][8][4];
    #pragma unroll
    for (int mi = 0; mi < 2; mi++)
        #pragma unroll
        for (int n8 = 0; n8 < 8; n8++)
            #pragma unroll
            for (int c = 0; c < 4; c++) acc[mi][n8][c] = 0.f;

    // ldmatrix lane-address components
    const uint32_t aOff = (uint32_t)((lane & 15)*SPB + (lane >> 4)*16);
    const uint32_t bOff = (uint32_t)(((lane & 7) + ((lane >> 4) << 3))*SPB + ((lane >> 3) & 1)*16);

    auto issue = [&](int s, int b) {
        const uint32_t base = sb + (uint32_t)b * STAGE_BYTES;
        #pragma unroll
        for (int mat = 0; mat < 4; mat++) {
            const __nv_bfloat16* gsrc = (mat==0) ? Xh : (mat==1) ? Xl : (mat==2) ? Wh : Wl;
            const int rbase = (mat < 2) ? m0 : n0;
            #pragma unroll
            for (int half = 0; half < 2; half++) {
                const int chunk = half*256 + tid;       // 0..511
                const int row = chunk >> 2, col = chunk & 3;
                cp16(base + (uint32_t)mat*MAT_BYTES + row*SPB + col*16,
                     gsrc + (size_t)(rbase + row) * D_MODEL + s*32 + col*8);
            }
        }
    };

    issue(0, 0); CP_COMMIT();

    for (int s = 0; s < D_MODEL/32; s++) {
        CP_WAIT0();        // stage s landed (own thread's copies)
        __syncthreads();   // publish stage s; close iter s-1 reads (issue-safety)
        if (s < D_MODEL/32 - 1) { issue(s+1, (s+1)&1); CP_COMMIT(); }

        const uint32_t Ahb = sb + (uint32_t)(s & 1) * STAGE_BYTES;
        const uint32_t Alb = Ahb + MAT_BYTES;
        const uint32_t Bhb = Ahb + 2*MAT_BYTES;
        const uint32_t Blb = Ahb + 3*MAT_BYTES;

        #pragma unroll
        for (int kk = 0; kk < 2; kk++) {
            uint32_t ah[2][4], al[2][4];
            #pragma unroll
            for (int mi = 0; mi < 2; mi++) {
                ldsm4(ah[mi], Ahb + (uint32_t)((mw*32 + mi*16)*SPB) + kk*32 + aOff);
                ldsm4(al[mi], Alb + (uint32_t)((mw*32 + mi*16)*SPB) + kk*32 + aOff);
            }
            #pragma unroll
            for (int np = 0; np < 4; np++) {
                uint32_t bh4[4], bl4[4];
                ldsm4(bh4, Bhb + (uint32_t)((nw*64 + np*16)*SPB) + kk*32 + bOff);
                ldsm4(bl4, Blb + (uint32_t)((nw*64 + np*16)*SPB) + kk*32 + bOff);
                #pragma unroll
                for (int mi = 0; mi < 2; mi++) {
                    mma16816(acc[mi][2*np],   ah[mi], bh4);
                    mma16816(acc[mi][2*np],   ah[mi], bl4);
                    mma16816(acc[mi][2*np],   al[mi], bh4);
                    mma16816(acc[mi][2*np+1], ah[mi], bh4+2);
                    mma16816(acc[mi][2*np+1], ah[mi], bl4+2);
                    mma16816(acc[mi][2*np+1], al[mi], bh4+2);
                }
            }
        }
    }

    // ---- register epilogue: thread holds rows (g, g+8), cols (2t, 2t+1) per n8 ----
    #pragma unroll
    for (int mi = 0; mi < 2; mi++) {
        const int r0 = m0 + mw*32 + mi*16 + g;
        const int r1 = r0 + 8;
        #pragma unroll
        for (int n8 = 0; n8 < 8; n8++) {
            const int ncol = n0 + nw*64 + n8*8 + t*2;
            const float2 bv2 = *reinterpret_cast<const float2*>(bias + ncol);
            float c00 = acc[mi][n8][0] + bv2.x, c01 = acc[mi][n8][1] + bv2.y;
            float c10 = acc[mi][n8][2] + bv2.x, c11 = acc[mi][n8][3] + bv2.y;
            if (OUT_MODE == 0) {
                c00 *= prescale; c01 *= prescale; c10 *= prescale; c11 *= prescale;
                const int h_ = ncol >> 6, d0 = ncol & 63;
                const size_t base0 = (((size_t)((r0 >> 11)*NHEADS + h_) * SEQ + (r0 & (SEQ-1))) * HDIM) + d0;
                const size_t base1 = (((size_t)((r1 >> 11)*NHEADS + h_) * SEQ + (r1 & (SEQ-1))) * HDIM) + d0;
                __nv_bfloat16 h0,l0,h1,l1;
                split2(c00,h0,l0); split2(c01,h1,l1);
                *reinterpret_cast<uint32_t*>(outH + base0) = packbf(h0,h1);
                *reinterpret_cast<uint32_t*>(outL + base0) = packbf(l0,l1);
                split2(c10,h0,l0); split2(c11,h1,l1);
                *reinterpret_cast<uint32_t*>(outH + base1) = packbf(h0,h1);
                *reinterpret_cast<uint32_t*>(outL + base1) = packbf(l0,l1);
            } else {
                float2* d0p = reinterpret_cast<float2*>(outF + (size_t)r0 * D_MODEL + ncol);
                float2* d1p = reinterpret_cast<float2*>(outF + (size_t)r1 * D_MODEL + ncol);
                *d0p = make_float2(c00, c01);
                *d1p = make_float2(c10, c11);
            }
        }
    }
}

__global__ __launch_bounds__(256, 2) void qkv_proj_kernel(
    const float* __restrict__ bq, const float* __restrict__ bk, const float* __restrict__ bv)
{
    if (blockIdx.z == 0)
        gemm_mma_body<0>(g_xqh, g_xql, g_wqh, g_wql, bq, g_qh, g_ql, nullptr, 8.0f);
    else if (blockIdx.z == 1)
        gemm_mma_body<0>(g_xkh, g_xkl, g_wkh, g_wkl, bk, g_kh, g_kl, nullptr, 1.0f);
    else
        gemm_mma_body<0>(g_xvh, g_xvl, g_wvh, g_wvl, bv, g_vh, g_vl, nullptr, 1.0f);
}

__global__ __launch_bounds__(256, 2) void out_proj_kernel(
    const float* __restrict__ bo, float* __restrict__ out)
{
    gemm_mma_body<1>(g_ah, g_al, g_woh, g_wol, bo, nullptr, nullptr, out, 1.0f);
}

// =====================================================================
// FA2-style flash attention: raw mma.sync, register softmax, register O.
// 128 q-rows/block, 8 warps, 64-key tiles. 2-deep cp.async K/V ring.
// SINGLE barrier per tile (same wait->barrier->issue ordering as GEMM).
// =====================================================================
#define PBB 144                            // row pitch bytes (72 bf16)
#define OFF_QH 0
#define OFF_QL (128*PBB)                   // 18432
#define OFF_KV (2*128*PBB)                 // 36864
#define KV_MAT (64*PBB)                    // 9216
#define KV_STAGE (4*KV_MAT)                // 36864 (Kh,Kl,Vh,Vl)
#define ATTN_SMEM (OFF_KV + 2*KV_STAGE)    // 110592

__global__ __launch_bounds__(256, 2) void flash_attn_mma()
{
    extern __shared__ __align__(128) char smem[];
    const uint32_t sb = smem_u32(smem);

    const int tid  = threadIdx.x;
    const int wid  = tid >> 5;
    const int lane = tid & 31;
    const int q0   = blockIdx.x * 128;
    const int bh   = blockIdx.y;
    const int g    = lane >> 2;
    const int t    = lane & 3;

    {
        const int r  = tid >> 1;
        const int ch = (tid & 1) * 32;
        const uint4* shp = reinterpret_cast<const uint4*>(g_qh + ((size_t)bh*SEQ + q0 + r)*HDIM + ch);
        const uint4* slp = reinterpret_cast<const uint4*>(g_ql + ((size_t)bh*SEQ + q0 + r)*HDIM + ch);
        uint4* dh = reinterpret_cast<uint4*>(smem + OFF_QH + r*PBB + ch*2);
        uint4* dl = reinterpret_cast<uint4*>(smem + OFF_QL + r*PBB + ch*2);
        #pragma unroll
        for (int i = 0; i < 4; i++) { dh[i] = shp[i]; dl[i] = slp[i]; }
    }

    const uint32_t qAddr = sb + OFF_QH + (uint32_t)((wid*16 + (lane & 15))*PBB + (lane >> 4)*16);
    const uint32_t kOff = (uint32_t)(((lane & 7) + ((lane >> 4) << 3)) * PBB + ((lane >> 3) & 1) * 16);
    const uint32_t vOff = (uint32_t)((((lane & 7) + (((lane >> 3) & 1) << 3)) * PBB) + ((lane >> 4) & 1) * 16);

    auto issueKV = [&](int kt, int b) {
        const uint32_t base = sb + OFF_KV + (uint32_t)b * KV_STAGE;
        #pragma unroll
        for (int mat = 0; mat < 4; mat++) {
            const __nv_bfloat16* gsrc = (mat==0) ? g_kh : (mat==1) ? g_kl : (mat==2) ? g_vh : g_vl;
            #pragma unroll
            for (int half = 0; half < 2; half++) {
                const int chunk = half*256 + tid;
                const int row = chunk >> 3, col = chunk & 7;
                cp16(base + (uint32_t)mat*KV_MAT + row*PBB + col*16,
                     gsrc + (size_t)(bh*SEQ + kt*64 + row) * HDIM + col*8);
            }
        }
    };

    float o[8][4];
    #pragma unroll
    for (int ni = 0; ni < 8; ni++)
        #pragma unroll
        for (int c = 0; c < 4; c++) o[ni][c] = 0.f;
    float m0 = -1e30f, m1 = -1e30f, l0 = 0.f, l1 = 0.f;

    issueKV(0, 0); CP_COMMIT();

    for (int kt = 0; kt < SEQ/64; kt++) {
        CP_WAIT0();        // K/V stage kt landed
        __syncthreads();   // publish stage kt (and Q on kt=0); close iter kt-1 reads
        if (kt < SEQ/64 - 1) { issueKV(kt+1, (kt+1)&1); CP_COMMIT(); }

        const uint32_t Kb  = sb + OFF_KV + (uint32_t)(kt & 1) * KV_STAGE;
        const uint32_t Klb = Kb + KV_MAT;
        const uint32_t Vb  = Kb + 2*KV_MAT;
        const uint32_t Vlb = Kb + 3*KV_MAT;

        float s[8][4];
        #pragma unroll
        for (int n8 = 0; n8 < 8; n8++)
            #pragma unroll
            for (int c = 0; c < 4; c++) s[n8][c] = 0.f;

        #pragma unroll
        for (int kk = 0; kk < 4; kk++) {
            uint32_t qh[4], ql[4];
            ldsm4(qh, qAddr + kk*32);
            ldsm4(ql, qAddr + (OFF_QL - OFF_QH) + kk*32);
            #pragma unroll
            for (int np = 0; np < 4; np++) {
                uint32_t bhf[4], blf[4];
                ldsm4(bhf, Kb  + np*16*PBB + kk*32 + kOff);
                ldsm4(blf, Klb + np*16*PBB + kk*32 + kOff);
                mma16816(s[2*np],   qh, bhf);     mma16816(s[2*np],   qh, blf);     mma16816(s[2*np],   ql, bhf);
                mma16816(s[2*np+1], qh, bhf+2);   mma16816(s[2*np+1], qh, blf+2);   mma16816(s[2*np+1], ql, bhf+2);
            }
        }

        float mx0 = -1e30f, mx1 = -1e30f;
        #pragma unroll
        for (int n8 = 0; n8 < 8; n8++) {
            mx0 = fmaxf(mx0, fmaxf(s[n8][0], s[n8][1]));
            mx1 = fmaxf(mx1, fmaxf(s[n8][2], s[n8][3]));
        }
        mx0 = fmaxf(mx0, __shfl_xor_sync(0xffffffffu, mx0, 1));
        mx0 = fmaxf(mx0, __shfl_xor_sync(0xffffffffu, mx0, 2));
        mx1 = fmaxf(mx1, __shfl_xor_sync(0xffffffffu, mx1, 1));
        mx1 = fmaxf(mx1, __shfl_xor_sync(0xffffffffu, mx1, 2));
        const float mn0 = fmaxf(m0, mx0), mn1 = fmaxf(m1, mx1);
        const float a0 = __expf(m0 - mn0), a1 = __expf(m1 - mn1);
        m0 = mn0; m1 = mn1;

        float sum0 = 0.f, sum1 = 0.f;
        #pragma unroll
        for (int n8 = 0; n8 < 8; n8++) {
            s[n8][0] = __expf(s[n8][0] - mn0);
            s[n8][1] = __expf(s[n8][1] - mn0);
            s[n8][2] = __expf(s[n8][2] - mn1);
            s[n8][3] = __expf(s[n8][3] - mn1);
            sum0 += s[n8][0] + s[n8][1];
            sum1 += s[n8][2] + s[n8][3];
        }
        sum0 += __shfl_xor_sync(0xffffffffu, sum0, 1);
        sum0 += __shfl_xor_sync(0xffffffffu, sum0, 2);
        sum1 += __shfl_xor_sync(0xffffffffu, sum1, 1);
        sum1 += __shfl_xor_sync(0xffffffffu, sum1, 2);
        l0 = l0*a0 + sum0;
        l1 = l1*a1 + sum1;

        #pragma unroll
        for (int ni = 0; ni < 8; ni++) {
            o[ni][0] *= a0; o[ni][1] *= a0;
            o[ni][2] *= a1; o[ni][3] *= a1;
        }

        #pragma unroll
        for (int kk = 0; kk < 4; kk++) {
            uint32_t ph[4], pl[4];
            {
                __nv_bfloat16 h00,l00,h01,l01,h02,l02,h03,l03;
                __nv_bfloat16 h10,l10,h11,l11,h12,l12,h13,l13;
                split2(s[2*kk][0],   h00, l00); split2(s[2*kk][1],   h01, l01);
                split2(s[2*kk][2],   h02, l02); split2(s[2*kk][3],   h03, l03);
                split2(s[2*kk+1][0], h10, l10); split2(s[2*kk+1][1], h11, l11);
                split2(s[2*kk+1][2], h12, l12); split2(s[2*kk+1][3], h13, l13);
                ph[0] = packbf(h00, h01); pl[0] = packbf(l00, l01);
                ph[1] = packbf(h02, h03); pl[1] = packbf(l02, l03);
                ph[2] = packbf(h10, h11); pl[2] = packbf(l10, l11);
                ph[3] = packbf(h12, h13); pl[3] = packbf(l12, l13);
            }
            #pragma unroll
            for (int np = 0; np < 4; np++) {
                uint32_t vh[4], vl[4];
                ldsm4t(vh, Vb  + kk*16*PBB + np*32 + vOff);
                ldsm4t(vl, Vlb + kk*16*PBB + np*32 + vOff);
                mma16816(o[2*np],   ph, vh);     mma16816(o[2*np],   ph, vl);     mma16816(o[2*np],   pl, vh);
                mma16816(o[2*np+1], ph, vh+2);   mma16816(o[2*np+1], ph, vl+2);   mma16816(o[2*np+1], pl, vh+2);
            }
        }
    }

    {
        const int b_ = bh / NHEADS;
        const int h_ = bh % NHEADS;
        const float i0 = 1.0f / l0, i1 = 1.0f / l1;
        const int r0 = q0 + wid*16 + g;
        const int r1 = r0 + 8;
        const size_t base0 = ((size_t)(b_*SEQ + r0)) * D_MODEL + h_*HDIM;
        const size_t base1 = ((size_t)(b_*SEQ + r1)) * D_MODEL + h_*HDIM;
        #pragma unroll
        for (int ni = 0; ni < 8; ni++) {
            const int col = ni*8 + t*2;
            __nv_bfloat16 h0,l0b,h1,l1b;
            split2(o[ni][0]*i0, h0, l0b); split2(o[ni][1]*i0, h1, l1b);
            *reinterpret_cast<uint32_t*>(g_ah + base0 + col) = packbf(h0, h1);
            *reinterpret_cast<uint32_t*>(g_al + base0 + col) = packbf(l0b, l1b);
            split2(o[ni][2]*i1, h0, l0b); split2(o[ni][3]*i1, h1, l1b);
            *reinterpret_cast<uint32_t*>(g_ah + base1 + col) = packbf(h0, h1);
            *reinterpret_cast<uint32_t*>(g_al + base1 + col) = packbf(l0b, l1b);
        }
    }
}

// =====================================================================
extern "C" void kernel_launch(void* const* d_in, const int* in_sizes, int n_in,
                              void* d_out, int out_size)
{
    const float* query = (const float*)d_in[0];
    const float* key   = (const float*)d_in[1];
    const float* value = (const float*)d_in[2];
    const float* Wq    = (const float*)d_in[3];
    const float* bq    = (const float*)d_in[4];
    const float* Wk    = (const float*)d_in[5];
    const float* bk    = (const float*)d_in[6];
    const float* Wv    = (const float*)d_in[7];
    const float* bv    = (const float*)d_in[8];
    const float* Wo    = (const float*)d_in[9];
    const float* bo    = (const float*)d_in[10];
    float* out = (float*)d_out;

    cudaFuncSetAttribute(qkv_proj_kernel, cudaFuncAttributeMaxDynamicSharedMemorySize, GEMM_SMEM);
    cudaFuncSetAttribute(out_proj_kernel, cudaFuncAttributeMaxDynamicSharedMemorySize, GEMM_SMEM);
    cudaFuncSetAttribute(flash_attn_mma, cudaFuncAttributeMaxDynamicSharedMemorySize, ATTN_SMEM);

    split_all_kernel<<<SPLIT_BLOCKS, 256>>>(query, key, value, Wq, Wk, Wv, Wo);

    dim3 qkv_grid(D_MODEL/128, MTOT/128, 3);   // (8, 32, 3)
    qkv_proj_kernel<<<qkv_grid, 256, GEMM_SMEM>>>(bq, bk, bv);

    dim3 attn_grid(SEQ/128, BATCH*NHEADS);     // (16, 32)
    flash_attn_mma<<<attn_grid, 256, ATTN_SMEM>>>();

    dim3 oproj_grid(D_MODEL/128, MTOT/128);    // (8, 32)
    out_proj_kernel<<<oproj_grid, 256, GEMM_SMEM>>>(bo, out);
}